// round 5
// baseline (speedup 1.0000x reference)
#include <cuda_runtime.h>
#include <cuda_bf16.h>
#include <math.h>
#include <stdint.h>

// ---------------- problem constants ----------------
#define S_     8
#define B_     128
#define N_     32
#define D_     1024
#define HEADS_ 16
#define DH_    64
#define Q_     64
#define INNER_ 1024
#define KVW_   2048          // 2*INNER
#define FFH_   4096          // INNER*MULT
#define FF2_   8192          // INNER*MULT*2
#define ROWS_  (S_*N_*Q_)    // 16384
#define KVROWS_ (S_*N_*B_)   // 32768

// ---------------- scratch (device globals) ----------------
__device__ float g_kv [(size_t)KVROWS_*KVW_];     // 268 MB
__device__ float g_att[(size_t)ROWS_*INNER_];     // 67 MB
__device__ float g_y  [(size_t)ROWS_*INNER_];     // 67 MB
__device__ float g_u  [(size_t)ROWS_*FF2_];       // 537 MB

__device__ __nv_bfloat16 g_xa_hi[(size_t)KVROWS_*D_];
__device__ __nv_bfloat16 g_xa_lo[(size_t)KVROWS_*D_];
__device__ __nv_bfloat16 g_wkt_hi[(size_t)KVW_*D_];
__device__ __nv_bfloat16 g_wkt_lo[(size_t)KVW_*D_];
__device__ __nv_bfloat16 g_w1t_hi[(size_t)FF2_*INNER_];
__device__ __nv_bfloat16 g_w1t_lo[(size_t)FF2_*INNER_];
__device__ __nv_bfloat16 g_w2t_hi[(size_t)INNER_*FFH_];
__device__ __nv_bfloat16 g_w2t_lo[(size_t)INNER_*FFH_];
__device__ __nv_bfloat16 g_y_hi [(size_t)ROWS_*INNER_];
__device__ __nv_bfloat16 g_y_lo [(size_t)ROWS_*INNER_];
__device__ __nv_bfloat16 g_h_hi [(size_t)ROWS_*FFH_];
__device__ __nv_bfloat16 g_h_lo [(size_t)ROWS_*FFH_];

// ---------------- helpers ----------------
__device__ __forceinline__ uint32_t smem_u32(const void* p) {
    uint32_t a;
    asm("{ .reg .u64 t; cvta.to.shared.u64 t, %1; cvt.u32.u64 %0, t; }" : "=r"(a) : "l"(p));
    return a;
}
__device__ __forceinline__ void ldsm_x4(uint32_t (&r)[4], uint32_t a) {
    asm volatile("ldmatrix.sync.aligned.m8n8.x4.shared.b16 {%0,%1,%2,%3}, [%4];"
        : "=r"(r[0]), "=r"(r[1]), "=r"(r[2]), "=r"(r[3]) : "r"(a));
}
__device__ __forceinline__ void mma16816(float (&c)[4], const uint32_t (&a)[4],
                                         uint32_t b0, uint32_t b1) {
    asm volatile("mma.sync.aligned.m16n8k16.row.col.f32.bf16.bf16.f32 "
        "{%0,%1,%2,%3}, {%4,%5,%6,%7}, {%8,%9}, {%0,%1,%2,%3};"
        : "+f"(c[0]), "+f"(c[1]), "+f"(c[2]), "+f"(c[3])
        : "r"(a[0]), "r"(a[1]), "r"(a[2]), "r"(a[3]), "r"(b0), "r"(b1));
}
__device__ __forceinline__ void split2(float v, __nv_bfloat16& h, __nv_bfloat16& l) {
    h = __float2bfloat16(v);
    l = __float2bfloat16(v - __bfloat162float(h));
}

// ---------------- bf16x3 split GEMM via mma.sync ----------------
// C[M,Nn] = A[M,K] @ B^T ; A as (Ah,Al) [M][K] bf16, B as (Bh,Bl) [Nn][K] bf16
// mode 0: plain; 1: +bias[n]; 2: +bias[n]+addmat[m][n]
// 1-D grid with 16-row-tile supertile rasterization for L2 reuse.
#define BKC 64                       // K per chunk
#define TILE_B 16384                 // 128 rows x 128 bytes
#define STAGE_B (4*TILE_B)           // Ah, Al, Bh, Bl
#define GEMM_SMEM (1024 + 3*STAGE_B) // 3 stages + alignment pad  (~193 KB)

__global__ __launch_bounds__(256) void mma_gemm(
    const __nv_bfloat16* __restrict__ Ah, const __nv_bfloat16* __restrict__ Al,
    const __nv_bfloat16* __restrict__ Bh, const __nv_bfloat16* __restrict__ Bl,
    float* __restrict__ C, int Nn, int K, int mode,
    const float* __restrict__ bias, const float* __restrict__ addmat)
{
    extern __shared__ char smem[];
    const uint32_t tiles = (smem_u32(smem) + 1023u) & ~1023u;
    const int tid = threadIdx.x;
    const int wid = tid >> 5, lid = tid & 31;

    // supertile raster: 16 row-tiles per group, sweep all column tiles
    const int tiles_n = Nn >> 7;
    const int bid = blockIdx.x;
    const int group = bid / (16 * tiles_n);
    const int rem = bid - group * 16 * tiles_n;
    const int row0 = ((group << 4) + (rem & 15)) << 7;
    const int col0 = (rem >> 4) << 7;

    const int wm = wid & 1;          // 2 M-groups of 64
    const int wn = wid >> 1;         // 4 N-groups of 32

    const __nv_bfloat16* a0 = Ah + (size_t)row0 * K;
    const __nv_bfloat16* a1 = Al + (size_t)row0 * K;
    const __nv_bfloat16* b0 = Bh + (size_t)col0 * K;
    const __nv_bfloat16* b1 = Bl + (size_t)col0 * K;

    const int nch = K / BKC;

    auto load_stage = [&](int st, int kc) {
        const uint32_t sb = tiles + st * STAGE_B;
        const int kB = kc * BKC * 2;          // byte offset in K
        #pragma unroll
        for (int j = 0; j < 4; j++) {
            const int i = j * 256 + tid;      // 0..1023
            const int r = i >> 3;             // 0..127
            const int c = i & 7;              // 16B chunk
            const uint32_t d = (uint32_t)(r * 128 + ((c * 16) ^ ((r & 7) * 16)));
            const size_t go = (size_t)r * K * 2 + kB + c * 16;
            asm volatile("cp.async.cg.shared.global [%0], [%1], 16;"
                :: "r"(sb + d), "l"((const char*)a0 + go));
            asm volatile("cp.async.cg.shared.global [%0], [%1], 16;"
                :: "r"(sb + TILE_B + d), "l"((const char*)a1 + go));
            asm volatile("cp.async.cg.shared.global [%0], [%1], 16;"
                :: "r"(sb + 2*TILE_B + d), "l"((const char*)b0 + go));
            asm volatile("cp.async.cg.shared.global [%0], [%1], 16;"
                :: "r"(sb + 3*TILE_B + d), "l"((const char*)b1 + go));
        }
        asm volatile("cp.async.commit_group;" ::: "memory");
    };

    float acc[4][4][4];
    #pragma unroll
    for (int i = 0; i < 4; i++)
        #pragma unroll
        for (int j = 0; j < 4; j++)
            #pragma unroll
            for (int t = 0; t < 4; t++) acc[i][j][t] = 0.f;

    const int lr = lid & 7;          // ldmatrix row within 8x8
    const int g  = lid >> 3;         // matrix group 0..3
    const uint32_t laneXor = (uint32_t)(lr * 16);

    load_stage(0, 0);
    load_stage(1, 1);
    load_stage(2, 2);

    for (int kc = 0; kc < nch; kc++) {
        const int st = kc % 3;
        asm volatile("cp.async.wait_group 2;" ::: "memory");
        __syncthreads();

        const uint32_t sb = tiles + st * STAGE_B;
        #pragma unroll
        for (int kk = 0; kk < 4; kk++) {
            const uint32_t cx = (uint32_t)((kk * 32 + (g >> 1) * 16)) ^ laneXor;
            uint32_t ah[4][4], al[4][4];
            #pragma unroll
            for (int i = 0; i < 4; i++) {
                const uint32_t row = (uint32_t)(wm * 64 + i * 16 + lr + (g & 1) * 8);
                const uint32_t off = row * 128 + cx;
                ldsm_x4(ah[i], sb + off);
                ldsm_x4(al[i], sb + TILE_B + off);
            }
            uint32_t bh[2][4], bl[2][4];
            #pragma unroll
            for (int jj = 0; jj < 2; jj++) {
                const uint32_t row = (uint32_t)(wn * 32 + jj * 16 + lr + (g & 1) * 8);
                const uint32_t off = row * 128 + cx;
                ldsm_x4(bh[jj], sb + 2*TILE_B + off);
                ldsm_x4(bl[jj], sb + 3*TILE_B + off);
            }
            // term-outer ordering: 8 independent accumulators between reuses
            #pragma unroll
            for (int i = 0; i < 4; i++)
                #pragma unroll
                for (int jj = 0; jj < 2; jj++) {
                    mma16816(acc[i][2*jj],   ah[i], bh[jj][0], bh[jj][2]);
                    mma16816(acc[i][2*jj+1], ah[i], bh[jj][1], bh[jj][3]);
                }
            #pragma unroll
            for (int i = 0; i < 4; i++)
                #pragma unroll
                for (int jj = 0; jj < 2; jj++) {
                    mma16816(acc[i][2*jj],   ah[i], bl[jj][0], bl[jj][2]);
                    mma16816(acc[i][2*jj+1], ah[i], bl[jj][1], bl[jj][3]);
                }
            #pragma unroll
            for (int i = 0; i < 4; i++)
                #pragma unroll
                for (int jj = 0; jj < 2; jj++) {
                    mma16816(acc[i][2*jj],   al[i], bh[jj][0], bh[jj][2]);
                    mma16816(acc[i][2*jj+1], al[i], bh[jj][1], bh[jj][3]);
                }
        }
        __syncthreads();
        if (kc + 3 < nch) load_stage(st, kc + 3);
    }

    // epilogue
    const int lr4 = lid >> 2, lc2 = (lid & 3) * 2;
    #pragma unroll
    for (int i = 0; i < 4; i++) {
        #pragma unroll
        for (int j = 0; j < 4; j++) {
            const int mr = row0 + wm * 64 + i * 16 + lr4;
            const int cc = col0 + wn * 32 + j * 8 + lc2;
            float2 v0 = make_float2(acc[i][j][0], acc[i][j][1]);
            float2 v1 = make_float2(acc[i][j][2], acc[i][j][3]);
            if (mode >= 1) {
                const float2 bb = *(const float2*)(bias + cc);
                v0.x += bb.x; v0.y += bb.y;
                v1.x += bb.x; v1.y += bb.y;
            }
            if (mode == 2) {
                const float2 am0 = *(const float2*)(addmat + (size_t)mr * Nn + cc);
                const float2 am1 = *(const float2*)(addmat + (size_t)(mr + 8) * Nn + cc);
                v0.x += am0.x; v0.y += am0.y;
                v1.x += am1.x; v1.y += am1.y;
            }
            *(float2*)(C + (size_t)mr * Nn + cc) = v0;
            *(float2*)(C + (size_t)(mr + 8) * Nn + cc) = v1;
        }
    }
}

// ---------------- prep: x (remap rows) -> bf16 hi/lo ----------------
__global__ __launch_bounds__(256) void prep_x_kernel(const float* __restrict__ x)
{
    const size_t i = (size_t)blockIdx.x * 256 + threadIdx.x;
    const size_t e = i << 2;
    const int m = (int)(e >> 10);
    const int col = (int)(e & 1023);
    const int s = m >> 12, rm = m & 4095, n = rm >> 7, b = rm & 127;
    const float4 v = *(const float4*)(x + (((size_t)((s * 128 + b) * 32 + n)) << 10) + col);
    __nv_bfloat16 h0, l0, h1, l1, h2, l2, h3, l3;
    split2(v.x, h0, l0); split2(v.y, h1, l1);
    split2(v.z, h2, l2); split2(v.w, h3, l3);
    *(__nv_bfloat162*)(g_xa_hi + e)     = __halves2bfloat162(h0, h1);
    *(__nv_bfloat162*)(g_xa_hi + e + 2) = __halves2bfloat162(h2, h3);
    *(__nv_bfloat162*)(g_xa_lo + e)     = __halves2bfloat162(l0, l1);
    *(__nv_bfloat162*)(g_xa_lo + e + 2) = __halves2bfloat162(l2, l3);
}

// ---------------- prep: transpose W [R][C] -> [C][R] bf16 hi/lo ----------------
__global__ __launch_bounds__(256) void tsplit_kernel(
    const float* __restrict__ in, __nv_bfloat16* __restrict__ oh,
    __nv_bfloat16* __restrict__ ol, int R, int C)
{
    __shared__ float tile[32][33];
    const int r0 = blockIdx.y * 32, c0 = blockIdx.x * 32;
    const int tx = threadIdx.x, ty = threadIdx.y;
    #pragma unroll
    for (int j = ty; j < 32; j += 8)
        tile[j][tx] = in[(size_t)(r0 + j) * C + c0 + tx];
    __syncthreads();
    #pragma unroll
    for (int j = ty; j < 32; j += 8) {
        const float v = tile[tx][j];
        __nv_bfloat16 h, l;
        split2(v, h, l);
        const size_t o = (size_t)(c0 + j) * R + r0 + tx;
        oh[o] = h; ol[o] = l;
    }
}

// ---------------- fused attention per (s,n,h) ----------------
#define ATTN_SMEM ((Q_*DH_ + B_*65 + Q_*B_) * (int)sizeof(float))

__global__ __launch_bounds__(256) void attn_kernel(
    const float* __restrict__ q, const int* __restrict__ mask)
{
    extern __shared__ float sm[];
    float* sQ  = sm;
    float* sKV = sQ + Q_ * DH_;
    float* sS  = sKV + B_ * 65;

    const int blk = blockIdx.x;
    const int s = blk / (N_ * HEADS_);
    const int n = (blk / HEADS_) % N_;
    const int h = blk % HEADS_;
    const int tid = threadIdx.x;

    for (int t = tid; t < Q_ * DH_; t += 256) {
        int qi = t >> 6, d = t & 63;
        sQ[t] = q[qi * INNER_ + h * DH_ + d];
    }
    const float* kvbase = g_kv + ((size_t)(s * N_ + n)) * B_ * KVW_;
    for (int t = tid; t < B_ * DH_; t += 256) {
        int j = t >> 6, d = t & 63;
        sKV[j * 65 + d] = kvbase[(size_t)j * KVW_ + h * DH_ + d];
    }
    __syncthreads();

    for (int t = tid; t < Q_ * B_; t += 256) {
        int qi = t >> 7, j = t & 127;
        const float* qp = sQ + qi * DH_;
        const float* kp = sKV + j * 65;
        float a = 0.f;
        #pragma unroll
        for (int d = 0; d < DH_; d++) a += qp[d] * kp[d];
        a *= 0.125f;
        if (mask[s * B_ + j] == 0) a = -1e10f;
        sS[qi * 128 + j] = a;
    }
    __syncthreads();

    const int warp = tid >> 5, lane = tid & 31;
    for (int r = warp * 8; r < warp * 8 + 8; r++) {
        float* row = sS + r * 128;
        float v0 = row[lane], v1 = row[lane + 32], v2 = row[lane + 64], v3 = row[lane + 96];
        float mx = fmaxf(fmaxf(v0, v1), fmaxf(v2, v3));
        #pragma unroll
        for (int o = 16; o > 0; o >>= 1) mx = fmaxf(mx, __shfl_xor_sync(0xffffffffu, mx, o));
        v0 = expf(v0 - mx); v1 = expf(v1 - mx); v2 = expf(v2 - mx); v3 = expf(v3 - mx);
        float sum = v0 + v1 + v2 + v3;
        #pragma unroll
        for (int o = 16; o > 0; o >>= 1) sum += __shfl_xor_sync(0xffffffffu, sum, o);
        float inv = 1.0f / sum;
        row[lane] = v0 * inv; row[lane + 32] = v1 * inv;
        row[lane + 64] = v2 * inv; row[lane + 96] = v3 * inv;
    }
    __syncthreads();

    for (int t = tid; t < B_ * DH_; t += 256) {
        int j = t >> 6, d = t & 63;
        sKV[j * 65 + d] = kvbase[(size_t)j * KVW_ + INNER_ + h * DH_ + d];
    }
    __syncthreads();

    float* outbase = g_att + ((size_t)(s * N_ + n)) * Q_ * INNER_;
    for (int t = tid; t < Q_ * DH_; t += 256) {
        int qi = t >> 6, d = t & 63;
        const float* ar = sS + qi * 128;
        float a = 0.f;
        #pragma unroll
        for (int j = 0; j < B_; j++) a += ar[j] * sKV[j * 65 + d];
        outbase[(size_t)qi * INNER_ + h * DH_ + d] = a;
    }
}

// ---------------- LayerNorm (fp32 y + bf16 hi/lo) ----------------
__global__ __launch_bounds__(256) void ln_kernel(
    const float* __restrict__ gamma, const float* __restrict__ beta)
{
    const int r = blockIdx.x;
    const float* xr = g_att + (size_t)r * INNER_;
    float* yr = g_y + (size_t)r * INNER_;
    const int tid = threadIdx.x;
    const int warp = tid >> 5, lane = tid & 31;

    float v[4];
    float sum = 0.f;
    #pragma unroll
    for (int i = 0; i < 4; i++) { v[i] = xr[tid + i * 256]; sum += v[i]; }

    __shared__ float red[8];
    #pragma unroll
    for (int o = 16; o > 0; o >>= 1) sum += __shfl_xor_sync(0xffffffffu, sum, o);
    if (lane == 0) red[warp] = sum;
    __syncthreads();
    float tot = red[lane & 7];
    #pragma unroll
    for (int o = 4; o > 0; o >>= 1) tot += __shfl_xor_sync(0xffffffffu, tot, o);
    float mean = tot * (1.0f / 1024.0f);

    float sq = 0.f;
    #pragma unroll
    for (int i = 0; i < 4; i++) { float d = v[i] - mean; sq += d * d; }
    #pragma unroll
    for (int o = 16; o > 0; o >>= 1) sq += __shfl_xor_sync(0xffffffffu, sq, o);
    __syncthreads();
    if (lane == 0) red[warp] = sq;
    __syncthreads();
    float tot2 = red[lane & 7];
    #pragma unroll
    for (int o = 4; o > 0; o >>= 1) tot2 += __shfl_xor_sync(0xffffffffu, tot2, o);
    float var = tot2 * (1.0f / 1024.0f);
    float inv = rsqrtf(var + 1e-5f);

    #pragma unroll
    for (int i = 0; i < 4; i++) {
        int c = tid + i * 256;
        float yv = (v[i] - mean) * inv * gamma[c] + beta[c];
        yr[c] = yv;
        __nv_bfloat16 h, l;
        split2(yv, h, l);
        g_y_hi[(size_t)r * INNER_ + c] = h;
        g_y_lo[(size_t)r * INNER_ + c] = l;
    }
}

// ---------------- GEGLU ----------------
__global__ __launch_bounds__(256) void geglu_kernel()
{
    const size_t i = (size_t)blockIdx.x * 256 + threadIdx.x;
    const size_t e = i << 2;
    const size_t r = e >> 12;
    const int c = (int)(e & 4095);
    const float4 a = *(const float4*)(g_u + r * FF2_ + c);
    const float4 g = *(const float4*)(g_u + r * FF2_ + FFH_ + c);
    float vals[4];
    vals[0] = a.x * (0.5f * g.x * (1.0f + erff(g.x * 0.70710678118654752f)));
    vals[1] = a.y * (0.5f * g.y * (1.0f + erff(g.y * 0.70710678118654752f)));
    vals[2] = a.z * (0.5f * g.z * (1.0f + erff(g.z * 0.70710678118654752f)));
    vals[3] = a.w * (0.5f * g.w * (1.0f + erff(g.w * 0.70710678118654752f)));
    __nv_bfloat16 h0, l0, h1, l1, h2, l2, h3, l3;
    split2(vals[0], h0, l0); split2(vals[1], h1, l1);
    split2(vals[2], h2, l2); split2(vals[3], h3, l3);
    *(__nv_bfloat162*)(g_h_hi + e)     = __halves2bfloat162(h0, h1);
    *(__nv_bfloat162*)(g_h_hi + e + 2) = __halves2bfloat162(h2, h3);
    *(__nv_bfloat162*)(g_h_lo + e)     = __halves2bfloat162(l0, l1);
    *(__nv_bfloat162*)(g_h_lo + e + 2) = __halves2bfloat162(l2, l3);
}

// ---------------- launch ----------------
extern "C" void kernel_launch(void* const* d_in, const int* in_sizes, int n_in,
                              void* d_out, int out_size)
{
    const float* x    = (const float*)d_in[0];
    const int*   mask = (const int*)  d_in[1];
    const float* q    = (const float*)d_in[2];
    const float* W_kv = (const float*)d_in[3];
    const float* ln_g = (const float*)d_in[4];
    const float* ln_b = (const float*)d_in[5];
    const float* W1   = (const float*)d_in[6];
    const float* b1   = (const float*)d_in[7];
    const float* W2   = (const float*)d_in[8];
    const float* b2   = (const float*)d_in[9];
    float* out = (float*)d_out;
    (void)in_sizes; (void)n_in; (void)out_size;

    float *kv, *y, *u;
    __nv_bfloat16 *xah, *xal, *wkh, *wkl, *w1h, *w1l, *w2h, *w2l, *yh, *yl, *hh, *hl;
    cudaGetSymbolAddress((void**)&kv,  g_kv);
    cudaGetSymbolAddress((void**)&y,   g_y);
    cudaGetSymbolAddress((void**)&u,   g_u);
    cudaGetSymbolAddress((void**)&xah, g_xa_hi);
    cudaGetSymbolAddress((void**)&xal, g_xa_lo);
    cudaGetSymbolAddress((void**)&wkh, g_wkt_hi);
    cudaGetSymbolAddress((void**)&wkl, g_wkt_lo);
    cudaGetSymbolAddress((void**)&w1h, g_w1t_hi);
    cudaGetSymbolAddress((void**)&w1l, g_w1t_lo);
    cudaGetSymbolAddress((void**)&w2h, g_w2t_hi);
    cudaGetSymbolAddress((void**)&w2l, g_w2t_lo);
    cudaGetSymbolAddress((void**)&yh,  g_y_hi);
    cudaGetSymbolAddress((void**)&yl,  g_y_lo);
    cudaGetSymbolAddress((void**)&hh,  g_h_hi);
    cudaGetSymbolAddress((void**)&hl,  g_h_lo);

    cudaFuncSetAttribute(attn_kernel, cudaFuncAttributeMaxDynamicSharedMemorySize, ATTN_SMEM);
    cudaFuncSetAttribute(mma_gemm,    cudaFuncAttributeMaxDynamicSharedMemorySize, GEMM_SMEM);

    // prep: split/transpose
    prep_x_kernel<<<(KVROWS_ * (size_t)D_) / 4 / 256, 256>>>(x);
    {
        dim3 b(32, 8);
        tsplit_kernel<<<dim3(KVW_ / 32, D_ / 32), b>>>(W_kv, wkh, wkl, D_, KVW_);
        tsplit_kernel<<<dim3(FF2_ / 32, INNER_ / 32), b>>>(W1, w1h, w1l, INNER_, FF2_);
        tsplit_kernel<<<dim3(INNER_ / 32, FFH_ / 32), b>>>(W2, w2h, w2l, FFH_, INNER_);
    }
    // 1) kv = x_t @ W_kv    (32768 x 2048, K=1024)
    mma_gemm<<<(KVROWS_ / 128) * (KVW_ / 128), 256, GEMM_SMEM>>>(
        xah, xal, wkh, wkl, kv, KVW_, D_, 0, nullptr, nullptr);
    // 2) attention -> g_att
    attn_kernel<<<S_ * N_ * HEADS_, 256, ATTN_SMEM>>>(q, mask);
    // 3) LayerNorm -> g_y (+ bf16 hi/lo)
    ln_kernel<<<ROWS_, 256>>>(ln_g, ln_b);
    // 4) u = y @ W1 + b1    (16384 x 8192, K=1024)
    mma_gemm<<<(ROWS_ / 128) * (FF2_ / 128), 256, GEMM_SMEM>>>(
        yh, yl, w1h, w1l, u, FF2_, INNER_, 1, b1, nullptr);
    // 5) geglu -> h hi/lo
    geglu_kernel<<<(ROWS_ * (size_t)FFH_) / 4 / 256, 256>>>();
    // 6) out = h @ W2 + b2 + y  (16384 x 1024, K=4096)
    mma_gemm<<<(ROWS_ / 128) * (INNER_ / 128), 256, GEMM_SMEM>>>(
        hh, hl, w2h, w2l, out, INNER_, FFH_, 2, b2, y);
}

// round 6
// speedup vs baseline: 1.4712x; 1.4712x over previous
#include <cuda_runtime.h>
#include <cuda_fp16.h>
#include <math.h>
#include <stdint.h>

// ---------------- problem constants ----------------
#define S_     8
#define B_     128
#define N_     32
#define D_     1024
#define HEADS_ 16
#define DH_    64
#define Q_     64
#define INNER_ 1024
#define KVW_   2048
#define FFH_   4096
#define FF2_   8192
#define ROWS_  (S_*N_*Q_)    // 16384
#define KVROWS_ (S_*N_*B_)   // 32768

// ---------------- scratch ----------------
__device__ float g_kv [(size_t)KVROWS_*KVW_];
__device__ float g_att[(size_t)ROWS_*INNER_];
__device__ float g_y  [(size_t)ROWS_*INNER_];

__device__ __half g_xa_hi[(size_t)KVROWS_*D_];
__device__ __half g_xa_lo[(size_t)KVROWS_*D_];
__device__ __half g_wkt [(size_t)KVW_*D_];
__device__ __half g_w1t [(size_t)FF2_*INNER_];
__device__ __half g_w2t [(size_t)INNER_*FFH_];
__device__ __half g_y_hi[(size_t)ROWS_*INNER_];
__device__ __half g_y_lo[(size_t)ROWS_*INNER_];
__device__ __half g_h_hi[(size_t)ROWS_*FFH_];
__device__ __half g_h_lo[(size_t)ROWS_*FFH_];

// ---------------- helpers ----------------
__device__ __forceinline__ uint32_t smem_u32(const void* p) {
    uint32_t a;
    asm("{ .reg .u64 t; cvta.to.shared.u64 t, %1; cvt.u32.u64 %0, t; }" : "=r"(a) : "l"(p));
    return a;
}
__device__ __forceinline__ void ldsm_x4(uint32_t (&r)[4], uint32_t a) {
    asm volatile("ldmatrix.sync.aligned.m8n8.x4.shared.b16 {%0,%1,%2,%3}, [%4];"
        : "=r"(r[0]), "=r"(r[1]), "=r"(r[2]), "=r"(r[3]) : "r"(a));
}
__device__ __forceinline__ void mma16816(float (&c)[4], const uint32_t (&a)[4],
                                         uint32_t b0, uint32_t b1) {
    asm volatile("mma.sync.aligned.m16n8k16.row.col.f32.f16.f16.f32 "
        "{%0,%1,%2,%3}, {%4,%5,%6,%7}, {%8,%9}, {%0,%1,%2,%3};"
        : "+f"(c[0]), "+f"(c[1]), "+f"(c[2]), "+f"(c[3])
        : "r"(a[0]), "r"(a[1]), "r"(a[2]), "r"(a[3]), "r"(b0), "r"(b1));
}
__device__ __forceinline__ void split2h(float v, __half& h, __half& l) {
    h = __float2half(v);
    l = __float2half(v - __half2float(h));
}

// ---------------- common GEMM tile constants ----------------
#define BKC 64
#define TILE_B 16384                     // 128 rows x 128 bytes
#define STAGE3_B (3*TILE_B)              // Ah, Al, Bh
#define STAGE4_B (4*TILE_B)              // Ah, Al, Ba, Bg
#define GEMM_SMEM  (1024 + 3*STAGE3_B)   // ~145 KB
#define GEGLU_SMEM (1024 + 3*STAGE4_B)   // ~193 KB

// ---------------- fp16x2 GEMM: C = A@B^T (+bias,+addmat) ----------------
// A as (Ah,Al) [M][K] half; B as single-half [Nn][K].
// mode 0: plain fp32 out; mode 2: +bias[n] +addmat[m][n]
__global__ __launch_bounds__(256) void mma_gemm(
    const __half* __restrict__ Ah, const __half* __restrict__ Al,
    const __half* __restrict__ Bh,
    float* __restrict__ C, int Nn, int K, int mode,
    const float* __restrict__ bias, const float* __restrict__ addmat)
{
    extern __shared__ char smem[];
    const uint32_t tiles = (smem_u32(smem) + 1023u) & ~1023u;
    const int tid = threadIdx.x;
    const int wid = tid >> 5, lid = tid & 31;

    const int tiles_n = Nn >> 7;
    const int bid = blockIdx.x;
    const int group = bid / (16 * tiles_n);
    const int rem = bid - group * 16 * tiles_n;
    const int row0 = ((group << 4) + (rem & 15)) << 7;
    const int col0 = (rem >> 4) << 7;

    const int wm = wid & 1;
    const int wn = wid >> 1;

    const __half* a0 = Ah + (size_t)row0 * K;
    const __half* a1 = Al + (size_t)row0 * K;
    const __half* b0 = Bh + (size_t)col0 * K;
    const int nch = K / BKC;

    auto load_stage = [&](int st, int kc) {
        const uint32_t sb = tiles + st * STAGE3_B;
        const int kB = kc * BKC * 2;
        #pragma unroll
        for (int j = 0; j < 4; j++) {
            const int i = j * 256 + tid;
            const int r = i >> 3;
            const int c = i & 7;
            const uint32_t d = (uint32_t)(r * 128 + ((c * 16) ^ ((r & 7) * 16)));
            const size_t go = (size_t)r * K * 2 + kB + c * 16;
            asm volatile("cp.async.cg.shared.global [%0], [%1], 16;"
                :: "r"(sb + d), "l"((const char*)a0 + go));
            asm volatile("cp.async.cg.shared.global [%0], [%1], 16;"
                :: "r"(sb + TILE_B + d), "l"((const char*)a1 + go));
            asm volatile("cp.async.cg.shared.global [%0], [%1], 16;"
                :: "r"(sb + 2*TILE_B + d), "l"((const char*)b0 + go));
        }
        asm volatile("cp.async.commit_group;" ::: "memory");
    };

    float acc[4][4][4];
    #pragma unroll
    for (int i = 0; i < 4; i++)
        #pragma unroll
        for (int j = 0; j < 4; j++)
            #pragma unroll
            for (int t = 0; t < 4; t++) acc[i][j][t] = 0.f;

    const int lr = lid & 7;
    const int g  = lid >> 3;
    const uint32_t laneXor = (uint32_t)(lr * 16);

    load_stage(0, 0); load_stage(1, 1); load_stage(2, 2);

    for (int kc = 0; kc < nch; kc++) {
        const int st = kc % 3;
        asm volatile("cp.async.wait_group 2;" ::: "memory");
        __syncthreads();
        const uint32_t sb = tiles + st * STAGE3_B;
        #pragma unroll
        for (int kk = 0; kk < 4; kk++) {
            const uint32_t cx = (uint32_t)((kk * 32 + (g >> 1) * 16)) ^ laneXor;
            uint32_t ah[4][4], al[4][4];
            #pragma unroll
            for (int i = 0; i < 4; i++) {
                const uint32_t row = (uint32_t)(wm * 64 + i * 16 + lr + (g & 1) * 8);
                const uint32_t off = row * 128 + cx;
                ldsm_x4(ah[i], sb + off);
                ldsm_x4(al[i], sb + TILE_B + off);
            }
            uint32_t bh[2][4];
            #pragma unroll
            for (int jj = 0; jj < 2; jj++) {
                const uint32_t row = (uint32_t)(wn * 32 + jj * 16 + lr + (g & 1) * 8);
                ldsm_x4(bh[jj], sb + 2*TILE_B + row * 128 + cx);
            }
            #pragma unroll
            for (int i = 0; i < 4; i++)
                #pragma unroll
                for (int jj = 0; jj < 2; jj++) {
                    mma16816(acc[i][2*jj],   ah[i], bh[jj][0], bh[jj][2]);
                    mma16816(acc[i][2*jj+1], ah[i], bh[jj][1], bh[jj][3]);
                }
            #pragma unroll
            for (int i = 0; i < 4; i++)
                #pragma unroll
                for (int jj = 0; jj < 2; jj++) {
                    mma16816(acc[i][2*jj],   al[i], bh[jj][0], bh[jj][2]);
                    mma16816(acc[i][2*jj+1], al[i], bh[jj][1], bh[jj][3]);
                }
        }
        __syncthreads();
        if (kc + 3 < nch) load_stage(st, kc + 3);
    }

    const int lr4 = lid >> 2, lc2 = (lid & 3) * 2;
    #pragma unroll
    for (int i = 0; i < 4; i++) {
        #pragma unroll
        for (int j = 0; j < 4; j++) {
            const int mr = row0 + wm * 64 + i * 16 + lr4;
            const int cc = col0 + wn * 32 + j * 8 + lc2;
            float2 v0 = make_float2(acc[i][j][0], acc[i][j][1]);
            float2 v1 = make_float2(acc[i][j][2], acc[i][j][3]);
            if (mode == 2) {
                const float2 bb = *(const float2*)(bias + cc);
                const float2 am0 = *(const float2*)(addmat + (size_t)mr * Nn + cc);
                const float2 am1 = *(const float2*)(addmat + (size_t)(mr + 8) * Nn + cc);
                v0.x += bb.x + am0.x; v0.y += bb.y + am0.y;
                v1.x += bb.x + am1.x; v1.y += bb.y + am1.y;
            }
            *(float2*)(C + (size_t)mr * Nn + cc) = v0;
            *(float2*)(C + (size_t)(mr + 8) * Nn + cc) = v1;
        }
    }
}

// ---------------- fused W1-GEMM + GEGLU ----------------
// u_a = y@W1[:, n], u_g = y@W1[:, n+4096]; h = (u_a+b1a)*gelu(u_g+b1g)
// writes h as half hi/lo. Grid over (ROWS/128) x (FFH/128).
__global__ __launch_bounds__(256) void mma_gemm_geglu(
    const __half* __restrict__ Ah, const __half* __restrict__ Al,
    const __half* __restrict__ Bt,      // W1^T [8192][1024]
    const float* __restrict__ bias)     // b1 [8192]
{
    extern __shared__ char smem[];
    const uint32_t tiles = (smem_u32(smem) + 1023u) & ~1023u;
    const int tid = threadIdx.x;
    const int wid = tid >> 5, lid = tid & 31;

    const int tiles_n = FFH_ >> 7;   // 32
    const int bid = blockIdx.x;
    const int group = bid / (16 * tiles_n);
    const int rem = bid - group * 16 * tiles_n;
    const int row0 = ((group << 4) + (rem & 15)) << 7;
    const int col0 = (rem >> 4) << 7;

    const int wm = wid & 1;
    const int wn = wid >> 1;
    const int K = INNER_;

    const __half* a0 = Ah + (size_t)row0 * K;
    const __half* a1 = Al + (size_t)row0 * K;
    const __half* ba = Bt + (size_t)col0 * K;
    const __half* bg = Bt + (size_t)(FFH_ + col0) * K;
    const int nch = K / BKC;

    auto load_stage = [&](int st, int kc) {
        const uint32_t sb = tiles + st * STAGE4_B;
        const int kB = kc * BKC * 2;
        #pragma unroll
        for (int j = 0; j < 4; j++) {
            const int i = j * 256 + tid;
            const int r = i >> 3;
            const int c = i & 7;
            const uint32_t d = (uint32_t)(r * 128 + ((c * 16) ^ ((r & 7) * 16)));
            const size_t go = (size_t)r * K * 2 + kB + c * 16;
            asm volatile("cp.async.cg.shared.global [%0], [%1], 16;"
                :: "r"(sb + d), "l"((const char*)a0 + go));
            asm volatile("cp.async.cg.shared.global [%0], [%1], 16;"
                :: "r"(sb + TILE_B + d), "l"((const char*)a1 + go));
            asm volatile("cp.async.cg.shared.global [%0], [%1], 16;"
                :: "r"(sb + 2*TILE_B + d), "l"((const char*)ba + go));
            asm volatile("cp.async.cg.shared.global [%0], [%1], 16;"
                :: "r"(sb + 3*TILE_B + d), "l"((const char*)bg + go));
        }
        asm volatile("cp.async.commit_group;" ::: "memory");
    };

    float acca[4][4][4], accg[4][4][4];
    #pragma unroll
    for (int i = 0; i < 4; i++)
        #pragma unroll
        for (int j = 0; j < 4; j++)
            #pragma unroll
            for (int t = 0; t < 4; t++) { acca[i][j][t] = 0.f; accg[i][j][t] = 0.f; }

    const int lr = lid & 7;
    const int g  = lid >> 3;
    const uint32_t laneXor = (uint32_t)(lr * 16);

    load_stage(0, 0); load_stage(1, 1); load_stage(2, 2);

    for (int kc = 0; kc < nch; kc++) {
        const int st = kc % 3;
        asm volatile("cp.async.wait_group 2;" ::: "memory");
        __syncthreads();
        const uint32_t sb = tiles + st * STAGE4_B;
        #pragma unroll
        for (int kk = 0; kk < 4; kk++) {
            const uint32_t cx = (uint32_t)((kk * 32 + (g >> 1) * 16)) ^ laneXor;
            uint32_t ah[4][4], al[4][4];
            #pragma unroll
            for (int i = 0; i < 4; i++) {
                const uint32_t row = (uint32_t)(wm * 64 + i * 16 + lr + (g & 1) * 8);
                const uint32_t off = row * 128 + cx;
                ldsm_x4(ah[i], sb + off);
                ldsm_x4(al[i], sb + TILE_B + off);
            }
            uint32_t bA[2][4], bG[2][4];
            #pragma unroll
            for (int jj = 0; jj < 2; jj++) {
                const uint32_t row = (uint32_t)(wn * 32 + jj * 16 + lr + (g & 1) * 8);
                ldsm_x4(bA[jj], sb + 2*TILE_B + row * 128 + cx);
                ldsm_x4(bG[jj], sb + 3*TILE_B + row * 128 + cx);
            }
            #pragma unroll
            for (int i = 0; i < 4; i++)
                #pragma unroll
                for (int jj = 0; jj < 2; jj++) {
                    mma16816(acca[i][2*jj],   ah[i], bA[jj][0], bA[jj][2]);
                    mma16816(acca[i][2*jj+1], ah[i], bA[jj][1], bA[jj][3]);
                    mma16816(accg[i][2*jj],   ah[i], bG[jj][0], bG[jj][2]);
                    mma16816(accg[i][2*jj+1], ah[i], bG[jj][1], bG[jj][3]);
                }
            #pragma unroll
            for (int i = 0; i < 4; i++)
                #pragma unroll
                for (int jj = 0; jj < 2; jj++) {
                    mma16816(acca[i][2*jj],   al[i], bA[jj][0], bA[jj][2]);
                    mma16816(acca[i][2*jj+1], al[i], bA[jj][1], bA[jj][3]);
                    mma16816(accg[i][2*jj],   al[i], bG[jj][0], bG[jj][2]);
                    mma16816(accg[i][2*jj+1], al[i], bG[jj][1], bG[jj][3]);
                }
        }
        __syncthreads();
        if (kc + 3 < nch) load_stage(st, kc + 3);
    }

    // epilogue: h = (ua + b1a) * gelu(ug + b1g), write half hi/lo
    const int lr4 = lid >> 2, lc2 = (lid & 3) * 2;
    #pragma unroll
    for (int i = 0; i < 4; i++) {
        #pragma unroll
        for (int j = 0; j < 4; j++) {
            const int mr = row0 + wm * 64 + i * 16 + lr4;
            const int cc = col0 + wn * 32 + j * 8 + lc2;
            const float2 bba = *(const float2*)(bias + cc);
            const float2 bbg = *(const float2*)(bias + FFH_ + cc);
            #pragma unroll
            for (int half_i = 0; half_i < 2; half_i++) {
                const int m = mr + half_i * 8;
                float av0 = acca[i][j][2*half_i]   + bba.x;
                float av1 = acca[i][j][2*half_i+1] + bba.y;
                float gv0 = accg[i][j][2*half_i]   + bbg.x;
                float gv1 = accg[i][j][2*half_i+1] + bbg.y;
                float h0 = av0 * (0.5f * gv0 * (1.0f + erff(gv0 * 0.70710678118654752f)));
                float h1 = av1 * (0.5f * gv1 * (1.0f + erff(gv1 * 0.70710678118654752f)));
                __half hh0, hl0, hh1, hl1;
                split2h(h0, hh0, hl0); split2h(h1, hh1, hl1);
                const size_t o = (size_t)m * FFH_ + cc;
                *(__half2*)(g_h_hi + o) = __halves2half2(hh0, hh1);
                *(__half2*)(g_h_lo + o) = __halves2half2(hl0, hl1);
            }
        }
    }
}

// ---------------- prep: x remap -> half hi/lo ----------------
__global__ __launch_bounds__(256) void prep_x_kernel(const float* __restrict__ x)
{
    const size_t i = (size_t)blockIdx.x * 256 + threadIdx.x;
    const size_t e = i << 2;
    const int m = (int)(e >> 10);
    const int col = (int)(e & 1023);
    const int s = m >> 12, rm = m & 4095, n = rm >> 7, b = rm & 127;
    const float4 v = *(const float4*)(x + (((size_t)((s * 128 + b) * 32 + n)) << 10) + col);
    __half h0, l0, h1, l1, h2, l2, h3, l3;
    split2h(v.x, h0, l0); split2h(v.y, h1, l1);
    split2h(v.z, h2, l2); split2h(v.w, h3, l3);
    *(__half2*)(g_xa_hi + e)     = __halves2half2(h0, h1);
    *(__half2*)(g_xa_hi + e + 2) = __halves2half2(h2, h3);
    *(__half2*)(g_xa_lo + e)     = __halves2half2(l0, l1);
    *(__half2*)(g_xa_lo + e + 2) = __halves2half2(l2, l3);
}

// ---------------- prep: transpose W -> single half ----------------
__global__ __launch_bounds__(256) void tsplit_kernel(
    const float* __restrict__ in, __half* __restrict__ oh, int R, int C)
{
    __shared__ float tile[32][33];
    const int r0 = blockIdx.y * 32, c0 = blockIdx.x * 32;
    const int tx = threadIdx.x, ty = threadIdx.y;
    #pragma unroll
    for (int j = ty; j < 32; j += 8)
        tile[j][tx] = in[(size_t)(r0 + j) * C + c0 + tx];
    __syncthreads();
    #pragma unroll
    for (int j = ty; j < 32; j += 8)
        oh[(size_t)(c0 + j) * R + r0 + tx] = __float2half(tile[tx][j]);
}

// ---------------- attention (micro-tiled fp32) ----------------
// smem: sQt[64][64], sKt[64][128] (reused as sV[128][64]), sS[64][128]
#define ATTN_SMEM ((DH_*Q_ + DH_*B_ + Q_*B_) * (int)sizeof(float))   // 80 KB

__global__ __launch_bounds__(256, 2) void attn_kernel(
    const float* __restrict__ q, const int* __restrict__ mask)
{
    extern __shared__ float sm[];
    float* sQt = sm;                  // [d][qi]  64x64
    float* sKt = sQt + DH_ * Q_;      // [d][j]   64x128 ; later sV [j][dv] 128x64
    float* sS  = sKt + DH_ * B_;      // [qi][j]  64x128

    const int blk = blockIdx.x;
    const int s = blk / (N_ * HEADS_);
    const int n = (blk / HEADS_) % N_;
    const int h = blk % HEADS_;
    const int tid = threadIdx.x;

    // load Q transposed: sQt[d][qi]
    for (int t = tid; t < Q_ * DH_; t += 256) {
        const int qi = t >> 6, d = t & 63;
        sQt[d * Q_ + qi] = q[qi * INNER_ + h * DH_ + d];
    }
    const float* kvbase = g_kv + ((size_t)(s * N_ + n)) * B_ * KVW_;
    // load K transposed: sKt[d][j]
    for (int t = tid; t < B_ * DH_; t += 256) {
        const int j = t >> 6, d = t & 63;
        sKt[d * B_ + j] = kvbase[(size_t)j * KVW_ + h * DH_ + d];
    }
    __syncthreads();

    // sim = Q@K^T * scale, masked. thread: tq=tid>>5 (qi-tiles tq, tq+8), tj=tid&31
    {
        const int tq = tid >> 5, tj = tid & 31;
        float acc[2][4][4];
        #pragma unroll
        for (int a = 0; a < 2; a++)
            #pragma unroll
            for (int i = 0; i < 4; i++)
                #pragma unroll
                for (int j = 0; j < 4; j++) acc[a][i][j] = 0.f;
        #pragma unroll 4
        for (int d = 0; d < DH_; d++) {
            const float4 rb  = *(const float4*)(sKt + d * B_ + tj * 4);
            const float4 ra0 = *(const float4*)(sQt + d * Q_ + tq * 4);
            const float4 ra1 = *(const float4*)(sQt + d * Q_ + (tq + 8) * 4);
            const float a0[4] = {ra0.x, ra0.y, ra0.z, ra0.w};
            const float a1[4] = {ra1.x, ra1.y, ra1.z, ra1.w};
            const float bb[4] = {rb.x, rb.y, rb.z, rb.w};
            #pragma unroll
            for (int i = 0; i < 4; i++)
                #pragma unroll
                for (int j = 0; j < 4; j++) {
                    acc[0][i][j] += a0[i] * bb[j];
                    acc[1][i][j] += a1[i] * bb[j];
                }
        }
        int mv[4];
        #pragma unroll
        for (int j = 0; j < 4; j++) mv[j] = mask[s * B_ + tj * 4 + j];
        #pragma unroll
        for (int a = 0; a < 2; a++)
            #pragma unroll
            for (int i = 0; i < 4; i++) {
                const int qi = (tq + 8 * a) * 4 + i;
                #pragma unroll
                for (int j = 0; j < 4; j++) {
                    float v = acc[a][i][j] * 0.125f;
                    if (mv[j] == 0) v = -1e10f;
                    sS[qi * B_ + tj * 4 + j] = v;
                }
            }
    }
    __syncthreads();

    // load V into sKt region: sV[j][dv]
    float* sV = sKt;
    for (int t = tid; t < B_ * DH_; t += 256) {
        const int j = t >> 6, dv = t & 63;
        sV[j * DH_ + dv] = kvbase[(size_t)j * KVW_ + INNER_ + h * DH_ + dv];
    }

    // softmax rows of sS (8 warps x 8 rows)
    {
        const int warp = tid >> 5, lane = tid & 31;
        for (int r = warp * 8; r < warp * 8 + 8; r++) {
            float* row = sS + r * B_;
            float v0 = row[lane], v1 = row[lane + 32], v2 = row[lane + 64], v3 = row[lane + 96];
            float mx = fmaxf(fmaxf(v0, v1), fmaxf(v2, v3));
            #pragma unroll
            for (int o = 16; o > 0; o >>= 1) mx = fmaxf(mx, __shfl_xor_sync(0xffffffffu, mx, o));
            v0 = expf(v0 - mx); v1 = expf(v1 - mx); v2 = expf(v2 - mx); v3 = expf(v3 - mx);
            float sum = v0 + v1 + v2 + v3;
            #pragma unroll
            for (int o = 16; o > 0; o >>= 1) sum += __shfl_xor_sync(0xffffffffu, sum, o);
            const float inv = 1.0f / sum;
            row[lane] = v0 * inv; row[lane + 32] = v1 * inv;
            row[lane + 64] = v2 * inv; row[lane + 96] = v3 * inv;
        }
    }
    __syncthreads();

    // out = P@V. thread: tq2=tid>>4 (qi-tile), tx2=tid&15 (dv-tile)
    {
        const int tq2 = tid >> 4, tx2 = tid & 15;
        float acc[4][4];
        #pragma unroll
        for (int i = 0; i < 4; i++)
            #pragma unroll
            for (int t = 0; t < 4; t++) acc[i][t] = 0.f;
        #pragma unroll 4
        for (int j = 0; j < B_; j++) {
            const float4 rb = *(const float4*)(sV + j * DH_ + tx2 * 4);
            const float bb[4] = {rb.x, rb.y, rb.z, rb.w};
            float pa[4];
            #pragma unroll
            for (int i = 0; i < 4; i++) pa[i] = sS[(tq2 * 4 + i) * B_ + j];
            #pragma unroll
            for (int i = 0; i < 4; i++)
                #pragma unroll
                for (int t = 0; t < 4; t++) acc[i][t] += pa[i] * bb[t];
        }
        float* outbase = g_att + ((size_t)(s * N_ + n)) * Q_ * INNER_;
        #pragma unroll
        for (int i = 0; i < 4; i++) {
            float4 v = make_float4(acc[i][0], acc[i][1], acc[i][2], acc[i][3]);
            *(float4*)(outbase + (size_t)(tq2 * 4 + i) * INNER_ + h * DH_ + tx2 * 4) = v;
        }
    }
}

// ---------------- LayerNorm (fp32 y + half hi/lo) ----------------
__global__ __launch_bounds__(256) void ln_kernel(
    const float* __restrict__ gamma, const float* __restrict__ beta)
{
    const int r = blockIdx.x;
    const float* xr = g_att + (size_t)r * INNER_;
    float* yr = g_y + (size_t)r * INNER_;
    const int tid = threadIdx.x;
    const int warp = tid >> 5, lane = tid & 31;

    float v[4];
    float sum = 0.f;
    #pragma unroll
    for (int i = 0; i < 4; i++) { v[i] = xr[tid + i * 256]; sum += v[i]; }

    __shared__ float red[8];
    #pragma unroll
    for (int o = 16; o > 0; o >>= 1) sum += __shfl_xor_sync(0xffffffffu, sum, o);
    if (lane == 0) red[warp] = sum;
    __syncthreads();
    float tot = red[lane & 7];
    #pragma unroll
    for (int o = 4; o > 0; o >>= 1) tot += __shfl_xor_sync(0xffffffffu, tot, o);
    float mean = tot * (1.0f / 1024.0f);

    float sq = 0.f;
    #pragma unroll
    for (int i = 0; i < 4; i++) { float d = v[i] - mean; sq += d * d; }
    #pragma unroll
    for (int o = 16; o > 0; o >>= 1) sq += __shfl_xor_sync(0xffffffffu, sq, o);
    __syncthreads();
    if (lane == 0) red[warp] = sq;
    __syncthreads();
    float tot2 = red[lane & 7];
    #pragma unroll
    for (int o = 4; o > 0; o >>= 1) tot2 += __shfl_xor_sync(0xffffffffu, tot2, o);
    float var = tot2 * (1.0f / 1024.0f);
    float inv = rsqrtf(var + 1e-5f);

    #pragma unroll
    for (int i = 0; i < 4; i++) {
        int c = tid + i * 256;
        float yv = (v[i] - mean) * inv * gamma[c] + beta[c];
        yr[c] = yv;
        __half h, l;
        split2h(yv, h, l);
        g_y_hi[(size_t)r * INNER_ + c] = h;
        g_y_lo[(size_t)r * INNER_ + c] = l;
    }
}

// ---------------- launch ----------------
extern "C" void kernel_launch(void* const* d_in, const int* in_sizes, int n_in,
                              void* d_out, int out_size)
{
    const float* x    = (const float*)d_in[0];
    const int*   mask = (const int*)  d_in[1];
    const float* q    = (const float*)d_in[2];
    const float* W_kv = (const float*)d_in[3];
    const float* ln_g = (const float*)d_in[4];
    const float* ln_b = (const float*)d_in[5];
    const float* W1   = (const float*)d_in[6];
    const float* b1   = (const float*)d_in[7];
    const float* W2   = (const float*)d_in[8];
    const float* b2   = (const float*)d_in[9];
    float* out = (float*)d_out;
    (void)in_sizes; (void)n_in; (void)out_size;

    float *kv, *y;
    __half *xah, *xal, *wkt, *w1t, *w2t, *yh, *yl, *hh, *hl;
    cudaGetSymbolAddress((void**)&kv,  g_kv);
    cudaGetSymbolAddress((void**)&y,   g_y);
    cudaGetSymbolAddress((void**)&xah, g_xa_hi);
    cudaGetSymbolAddress((void**)&xal, g_xa_lo);
    cudaGetSymbolAddress((void**)&wkt, g_wkt);
    cudaGetSymbolAddress((void**)&w1t, g_w1t);
    cudaGetSymbolAddress((void**)&w2t, g_w2t);
    cudaGetSymbolAddress((void**)&yh,  g_y_hi);
    cudaGetSymbolAddress((void**)&yl,  g_y_lo);
    cudaGetSymbolAddress((void**)&hh,  g_h_hi);
    cudaGetSymbolAddress((void**)&hl,  g_h_lo);

    cudaFuncSetAttribute(attn_kernel,    cudaFuncAttributeMaxDynamicSharedMemorySize, ATTN_SMEM);
    cudaFuncSetAttribute(mma_gemm,       cudaFuncAttributeMaxDynamicSharedMemorySize, GEMM_SMEM);
    cudaFuncSetAttribute(mma_gemm_geglu, cudaFuncAttributeMaxDynamicSharedMemorySize, GEGLU_SMEM);

    // prep
    prep_x_kernel<<<(KVROWS_ * (size_t)D_) / 4 / 256, 256>>>(x);
    {
        dim3 b(32, 8);
        tsplit_kernel<<<dim3(KVW_ / 32, D_ / 32), b>>>(W_kv, wkt, D_, KVW_);
        tsplit_kernel<<<dim3(FF2_ / 32, INNER_ / 32), b>>>(W1, w1t, INNER_, FF2_);
        tsplit_kernel<<<dim3(INNER_ / 32, FFH_ / 32), b>>>(W2, w2t, FFH_, INNER_);
    }
    // 1) kv = x_t @ W_kv
    mma_gemm<<<(KVROWS_ / 128) * (KVW_ / 128), 256, GEMM_SMEM>>>(
        xah, xal, wkt, kv, KVW_, D_, 0, nullptr, nullptr);
    // 2) attention -> g_att
    attn_kernel<<<S_ * N_ * HEADS_, 256, ATTN_SMEM>>>(q, mask);
    // 3) LayerNorm -> g_y (+ half hi/lo)
    ln_kernel<<<ROWS_, 256>>>(ln_g, ln_b);
    // 4+5) u = y@W1 + b1; h = geglu(u)  (fused)
    mma_gemm_geglu<<<(ROWS_ / 128) * (FFH_ / 128), 256, GEGLU_SMEM>>>(
        yh, yl, w1t, b1);
    // 6) out = h@W2 + b2 + y
    mma_gemm<<<(ROWS_ / 128) * (INNER_ / 128), 256, GEMM_SMEM>>>(
        hh, hl, w2t, out, INNER_, FFH_, 2, b2, y);
}

// round 7
// speedup vs baseline: 2.6320x; 1.7891x over previous
#include <cuda_runtime.h>
#include <cuda_fp16.h>
#include <math.h>
#include <stdint.h>

// ---------------- problem constants ----------------
#define S_     8
#define B_     128
#define N_     32
#define D_     1024
#define HEADS_ 16
#define DH_    64
#define Q_     64
#define INNER_ 1024
#define KVW_   2048
#define FFH_   4096
#define FF2_   8192
#define ROWS_  (S_*N_*Q_)    // 16384
#define KVROWS_ (S_*N_*B_)   // 32768

// ---------------- scratch ----------------
__device__ float g_kv [(size_t)KVROWS_*KVW_];
__device__ float g_att[(size_t)ROWS_*INNER_];
__device__ float g_y  [(size_t)ROWS_*INNER_];

__device__ __half g_xa [(size_t)KVROWS_*D_];
__device__ __half g_wkt[(size_t)KVW_*D_];
__device__ __half g_w1t[(size_t)FF2_*INNER_];
__device__ __half g_w2t[(size_t)INNER_*FFH_];
__device__ __half g_yh [(size_t)ROWS_*INNER_];
__device__ __half g_hh [(size_t)ROWS_*FFH_];

// ---------------- helpers ----------------
__device__ __forceinline__ uint32_t smem_u32(const void* p) {
    uint32_t a;
    asm("{ .reg .u64 t; cvta.to.shared.u64 t, %1; cvt.u32.u64 %0, t; }" : "=r"(a) : "l"(p));
    return a;
}
__device__ __forceinline__ void ldsm_x4(uint32_t (&r)[4], uint32_t a) {
    asm volatile("ldmatrix.sync.aligned.m8n8.x4.shared.b16 {%0,%1,%2,%3}, [%4];"
        : "=r"(r[0]), "=r"(r[1]), "=r"(r[2]), "=r"(r[3]) : "r"(a));
}
__device__ __forceinline__ void mma16816(float (&c)[4], const uint32_t (&a)[4],
                                         uint32_t b0, uint32_t b1) {
    asm volatile("mma.sync.aligned.m16n8k16.row.col.f32.f16.f16.f32 "
        "{%0,%1,%2,%3}, {%4,%5,%6,%7}, {%8,%9}, {%0,%1,%2,%3};"
        : "+f"(c[0]), "+f"(c[1]), "+f"(c[2]), "+f"(c[3])
        : "r"(a[0]), "r"(a[1]), "r"(a[2]), "r"(a[3]), "r"(b0), "r"(b1));
}

// ---------------- common GEMM tile constants ----------------
#define BKC 64
#define TILE_B 16384                     // 128 rows x 128 bytes
#define STAGE2_B (2*TILE_B)              // A, B
#define STAGE3_B (3*TILE_B)              // A, Ba, Bg
#define GEMM_SMEM  (1024 + 3*STAGE2_B)   // ~97 KB
#define GEGLU_SMEM (1024 + 3*STAGE3_B)   // ~145 KB

// ---------------- fp16 GEMM: C = A@B^T (+bias,+addmat) ----------------
// A [M][K] half; B [Nn][K] half (pre-transposed weights).
// mode 0: plain fp32 out; mode 2: +bias[n] +addmat[m][n]
__global__ __launch_bounds__(256) void mma_gemm(
    const __half* __restrict__ Ah, const __half* __restrict__ Bh,
    float* __restrict__ C, int Nn, int K, int mode,
    const float* __restrict__ bias, const float* __restrict__ addmat)
{
    extern __shared__ char smem[];
    const uint32_t tiles = (smem_u32(smem) + 1023u) & ~1023u;
    const int tid = threadIdx.x;
    const int wid = tid >> 5, lid = tid & 31;

    const int tiles_n = Nn >> 7;
    const int bid = blockIdx.x;
    const int group = bid / (16 * tiles_n);
    const int rem = bid - group * 16 * tiles_n;
    const int row0 = ((group << 4) + (rem & 15)) << 7;
    const int col0 = (rem >> 4) << 7;

    const int wm = wid & 1;
    const int wn = wid >> 1;

    const __half* a0 = Ah + (size_t)row0 * K;
    const __half* b0 = Bh + (size_t)col0 * K;
    const int nch = K / BKC;

    auto load_stage = [&](int st, int kc) {
        const uint32_t sb = tiles + st * STAGE2_B;
        const int kB = kc * BKC * 2;
        #pragma unroll
        for (int j = 0; j < 4; j++) {
            const int i = j * 256 + tid;
            const int r = i >> 3;
            const int c = i & 7;
            const uint32_t d = (uint32_t)(r * 128 + ((c * 16) ^ ((r & 7) * 16)));
            const size_t go = (size_t)r * K * 2 + kB + c * 16;
            asm volatile("cp.async.cg.shared.global [%0], [%1], 16;"
                :: "r"(sb + d), "l"((const char*)a0 + go));
            asm volatile("cp.async.cg.shared.global [%0], [%1], 16;"
                :: "r"(sb + TILE_B + d), "l"((const char*)b0 + go));
        }
        asm volatile("cp.async.commit_group;" ::: "memory");
    };

    float acc[4][4][4];
    #pragma unroll
    for (int i = 0; i < 4; i++)
        #pragma unroll
        for (int j = 0; j < 4; j++)
            #pragma unroll
            for (int t = 0; t < 4; t++) acc[i][j][t] = 0.f;

    const int lr = lid & 7;
    const int g  = lid >> 3;
    const uint32_t laneXor = (uint32_t)(lr * 16);

    load_stage(0, 0); load_stage(1, 1); load_stage(2, 2);

    for (int kc = 0; kc < nch; kc++) {
        const int st = kc % 3;
        asm volatile("cp.async.wait_group 2;" ::: "memory");
        __syncthreads();
        const uint32_t sb = tiles + st * STAGE2_B;
        #pragma unroll
        for (int kk = 0; kk < 4; kk++) {
            const uint32_t cx = (uint32_t)((kk * 32 + (g >> 1) * 16)) ^ laneXor;
            uint32_t a[4][4];
            #pragma unroll
            for (int i = 0; i < 4; i++) {
                const uint32_t row = (uint32_t)(wm * 64 + i * 16 + lr + (g & 1) * 8);
                ldsm_x4(a[i], sb + row * 128 + cx);
            }
            uint32_t b[2][4];
            #pragma unroll
            for (int jj = 0; jj < 2; jj++) {
                const uint32_t row = (uint32_t)(wn * 32 + jj * 16 + lr + (g & 1) * 8);
                ldsm_x4(b[jj], sb + TILE_B + row * 128 + cx);
            }
            #pragma unroll
            for (int i = 0; i < 4; i++)
                #pragma unroll
                for (int jj = 0; jj < 2; jj++) {
                    mma16816(acc[i][2*jj],   a[i], b[jj][0], b[jj][2]);
                    mma16816(acc[i][2*jj+1], a[i], b[jj][1], b[jj][3]);
                }
        }
        __syncthreads();
        if (kc + 3 < nch) load_stage(st, kc + 3);
    }

    const int lr4 = lid >> 2, lc2 = (lid & 3) * 2;
    #pragma unroll
    for (int i = 0; i < 4; i++) {
        #pragma unroll
        for (int j = 0; j < 4; j++) {
            const int mr = row0 + wm * 64 + i * 16 + lr4;
            const int cc = col0 + wn * 32 + j * 8 + lc2;
            float2 v0 = make_float2(acc[i][j][0], acc[i][j][1]);
            float2 v1 = make_float2(acc[i][j][2], acc[i][j][3]);
            if (mode == 2) {
                const float2 bb = *(const float2*)(bias + cc);
                const float2 am0 = *(const float2*)(addmat + (size_t)mr * Nn + cc);
                const float2 am1 = *(const float2*)(addmat + (size_t)(mr + 8) * Nn + cc);
                v0.x += bb.x + am0.x; v0.y += bb.y + am0.y;
                v1.x += bb.x + am1.x; v1.y += bb.y + am1.y;
            }
            *(float2*)(C + (size_t)mr * Nn + cc) = v0;
            *(float2*)(C + (size_t)(mr + 8) * Nn + cc) = v1;
        }
    }
}

// ---------------- fused W1-GEMM + GEGLU ----------------
// u_a = y@W1[:, n], u_g = y@W1[:, n+4096]; h = (u_a+b1a)*gelu(u_g+b1g)
__global__ __launch_bounds__(256) void mma_gemm_geglu(
    const __half* __restrict__ Ah,
    const __half* __restrict__ Bt,      // W1^T [8192][1024]
    const float* __restrict__ bias)     // b1 [8192]
{
    extern __shared__ char smem[];
    const uint32_t tiles = (smem_u32(smem) + 1023u) & ~1023u;
    const int tid = threadIdx.x;
    const int wid = tid >> 5, lid = tid & 31;

    const int tiles_n = FFH_ >> 7;   // 32
    const int bid = blockIdx.x;
    const int group = bid / (16 * tiles_n);
    const int rem = bid - group * 16 * tiles_n;
    const int row0 = ((group << 4) + (rem & 15)) << 7;
    const int col0 = (rem >> 4) << 7;

    const int wm = wid & 1;
    const int wn = wid >> 1;
    const int K = INNER_;

    const __half* a0 = Ah + (size_t)row0 * K;
    const __half* ba = Bt + (size_t)col0 * K;
    const __half* bg = Bt + (size_t)(FFH_ + col0) * K;
    const int nch = K / BKC;

    auto load_stage = [&](int st, int kc) {
        const uint32_t sb = tiles + st * STAGE3_B;
        const int kB = kc * BKC * 2;
        #pragma unroll
        for (int j = 0; j < 4; j++) {
            const int i = j * 256 + tid;
            const int r = i >> 3;
            const int c = i & 7;
            const uint32_t d = (uint32_t)(r * 128 + ((c * 16) ^ ((r & 7) * 16)));
            const size_t go = (size_t)r * K * 2 + kB + c * 16;
            asm volatile("cp.async.cg.shared.global [%0], [%1], 16;"
                :: "r"(sb + d), "l"((const char*)a0 + go));
            asm volatile("cp.async.cg.shared.global [%0], [%1], 16;"
                :: "r"(sb + TILE_B + d), "l"((const char*)ba + go));
            asm volatile("cp.async.cg.shared.global [%0], [%1], 16;"
                :: "r"(sb + 2*TILE_B + d), "l"((const char*)bg + go));
        }
        asm volatile("cp.async.commit_group;" ::: "memory");
    };

    float acca[4][4][4], accg[4][4][4];
    #pragma unroll
    for (int i = 0; i < 4; i++)
        #pragma unroll
        for (int j = 0; j < 4; j++)
            #pragma unroll
            for (int t = 0; t < 4; t++) { acca[i][j][t] = 0.f; accg[i][j][t] = 0.f; }

    const int lr = lid & 7;
    const int g  = lid >> 3;
    const uint32_t laneXor = (uint32_t)(lr * 16);

    load_stage(0, 0); load_stage(1, 1); load_stage(2, 2);

    for (int kc = 0; kc < nch; kc++) {
        const int st = kc % 3;
        asm volatile("cp.async.wait_group 2;" ::: "memory");
        __syncthreads();
        const uint32_t sb = tiles + st * STAGE3_B;
        #pragma unroll
        for (int kk = 0; kk < 4; kk++) {
            const uint32_t cx = (uint32_t)((kk * 32 + (g >> 1) * 16)) ^ laneXor;
            uint32_t a[4][4];
            #pragma unroll
            for (int i = 0; i < 4; i++) {
                const uint32_t row = (uint32_t)(wm * 64 + i * 16 + lr + (g & 1) * 8);
                ldsm_x4(a[i], sb + row * 128 + cx);
            }
            uint32_t bA[2][4], bG[2][4];
            #pragma unroll
            for (int jj = 0; jj < 2; jj++) {
                const uint32_t row = (uint32_t)(wn * 32 + jj * 16 + lr + (g & 1) * 8);
                ldsm_x4(bA[jj], sb + TILE_B + row * 128 + cx);
                ldsm_x4(bG[jj], sb + 2*TILE_B + row * 128 + cx);
            }
            #pragma unroll
            for (int i = 0; i < 4; i++)
                #pragma unroll
                for (int jj = 0; jj < 2; jj++) {
                    mma16816(acca[i][2*jj],   a[i], bA[jj][0], bA[jj][2]);
                    mma16816(acca[i][2*jj+1], a[i], bA[jj][1], bA[jj][3]);
                    mma16816(accg[i][2*jj],   a[i], bG[jj][0], bG[jj][2]);
                    mma16816(accg[i][2*jj+1], a[i], bG[jj][1], bG[jj][3]);
                }
        }
        __syncthreads();
        if (kc + 3 < nch) load_stage(st, kc + 3);
    }

    // epilogue: h = (ua + b1a) * gelu(ug + b1g), write half
    const int lr4 = lid >> 2, lc2 = (lid & 3) * 2;
    #pragma unroll
    for (int i = 0; i < 4; i++) {
        #pragma unroll
        for (int j = 0; j < 4; j++) {
            const int mr = row0 + wm * 64 + i * 16 + lr4;
            const int cc = col0 + wn * 32 + j * 8 + lc2;
            const float2 bba = *(const float2*)(bias + cc);
            const float2 bbg = *(const float2*)(bias + FFH_ + cc);
            #pragma unroll
            for (int half_i = 0; half_i < 2; half_i++) {
                const int m = mr + half_i * 8;
                float av0 = acca[i][j][2*half_i]   + bba.x;
                float av1 = acca[i][j][2*half_i+1] + bba.y;
                float gv0 = accg[i][j][2*half_i]   + bbg.x;
                float gv1 = accg[i][j][2*half_i+1] + bbg.y;
                float h0 = av0 * (0.5f * gv0 * (1.0f + erff(gv0 * 0.70710678118654752f)));
                float h1 = av1 * (0.5f * gv1 * (1.0f + erff(gv1 * 0.70710678118654752f)));
                *(__half2*)(g_hh + (size_t)m * FFH_ + cc) =
                    __halves2half2(__float2half(h0), __float2half(h1));
            }
        }
    }
}

// ---------------- prep: x remap -> half ----------------
__global__ __launch_bounds__(256) void prep_x_kernel(const float* __restrict__ x)
{
    const size_t i = (size_t)blockIdx.x * 256 + threadIdx.x;
    const size_t e = i << 2;
    const int m = (int)(e >> 10);
    const int col = (int)(e & 1023);
    const int s = m >> 12, rm = m & 4095, n = rm >> 7, b = rm & 127;
    const float4 v = *(const float4*)(x + (((size_t)((s * 128 + b) * 32 + n)) << 10) + col);
    *(__half2*)(g_xa + e)     = __halves2half2(__float2half(v.x), __float2half(v.y));
    *(__half2*)(g_xa + e + 2) = __halves2half2(__float2half(v.z), __float2half(v.w));
}

// ---------------- prep: transpose W -> half ----------------
__global__ __launch_bounds__(256) void tsplit_kernel(
    const float* __restrict__ in, __half* __restrict__ oh, int R, int C)
{
    __shared__ float tile[32][33];
    const int r0 = blockIdx.y * 32, c0 = blockIdx.x * 32;
    const int tx = threadIdx.x, ty = threadIdx.y;
    #pragma unroll
    for (int j = ty; j < 32; j += 8)
        tile[j][tx] = in[(size_t)(r0 + j) * C + c0 + tx];
    __syncthreads();
    #pragma unroll
    for (int j = ty; j < 32; j += 8)
        oh[(size_t)(c0 + j) * R + r0 + tx] = __float2half(tile[tx][j]);
}

// ---------------- attention (micro-tiled fp32) ----------------
#define ATTN_SMEM ((DH_*Q_ + DH_*B_ + Q_*B_) * (int)sizeof(float))   // 80 KB

__global__ __launch_bounds__(256, 2) void attn_kernel(
    const float* __restrict__ q, const int* __restrict__ mask)
{
    extern __shared__ float sm[];
    float* sQt = sm;                  // [d][qi]  64x64
    float* sKt = sQt + DH_ * Q_;      // [d][j]   64x128 ; later sV [j][dv] 128x64
    float* sS  = sKt + DH_ * B_;      // [qi][j]  64x128

    const int blk = blockIdx.x;
    const int s = blk / (N_ * HEADS_);
    const int n = (blk / HEADS_) % N_;
    const int h = blk % HEADS_;
    const int tid = threadIdx.x;

    for (int t = tid; t < Q_ * DH_; t += 256) {
        const int qi = t >> 6, d = t & 63;
        sQt[d * Q_ + qi] = q[qi * INNER_ + h * DH_ + d];
    }
    const float* kvbase = g_kv + ((size_t)(s * N_ + n)) * B_ * KVW_;
    for (int t = tid; t < B_ * DH_; t += 256) {
        const int j = t >> 6, d = t & 63;
        sKt[d * B_ + j] = kvbase[(size_t)j * KVW_ + h * DH_ + d];
    }
    __syncthreads();

    {
        const int tq = tid >> 5, tj = tid & 31;
        float acc[2][4][4];
        #pragma unroll
        for (int a = 0; a < 2; a++)
            #pragma unroll
            for (int i = 0; i < 4; i++)
                #pragma unroll
                for (int j = 0; j < 4; j++) acc[a][i][j] = 0.f;
        #pragma unroll 4
        for (int d = 0; d < DH_; d++) {
            const float4 rb  = *(const float4*)(sKt + d * B_ + tj * 4);
            const float4 ra0 = *(const float4*)(sQt + d * Q_ + tq * 4);
            const float4 ra1 = *(const float4*)(sQt + d * Q_ + (tq + 8) * 4);
            const float a0[4] = {ra0.x, ra0.y, ra0.z, ra0.w};
            const float a1[4] = {ra1.x, ra1.y, ra1.z, ra1.w};
            const float bb[4] = {rb.x, rb.y, rb.z, rb.w};
            #pragma unroll
            for (int i = 0; i < 4; i++)
                #pragma unroll
                for (int j = 0; j < 4; j++) {
                    acc[0][i][j] += a0[i] * bb[j];
                    acc[1][i][j] += a1[i] * bb[j];
                }
        }
        int mv[4];
        #pragma unroll
        for (int j = 0; j < 4; j++) mv[j] = mask[s * B_ + tj * 4 + j];
        #pragma unroll
        for (int a = 0; a < 2; a++)
            #pragma unroll
            for (int i = 0; i < 4; i++) {
                const int qi = (tq + 8 * a) * 4 + i;
                #pragma unroll
                for (int j = 0; j < 4; j++) {
                    float v = acc[a][i][j] * 0.125f;
                    if (mv[j] == 0) v = -1e10f;
                    sS[qi * B_ + tj * 4 + j] = v;
                }
            }
    }
    __syncthreads();

    float* sV = sKt;
    for (int t = tid; t < B_ * DH_; t += 256) {
        const int j = t >> 6, dv = t & 63;
        sV[j * DH_ + dv] = kvbase[(size_t)j * KVW_ + INNER_ + h * DH_ + dv];
    }

    {
        const int warp = tid >> 5, lane = tid & 31;
        for (int r = warp * 8; r < warp * 8 + 8; r++) {
            float* row = sS + r * B_;
            float v0 = row[lane], v1 = row[lane + 32], v2 = row[lane + 64], v3 = row[lane + 96];
            float mx = fmaxf(fmaxf(v0, v1), fmaxf(v2, v3));
            #pragma unroll
            for (int o = 16; o > 0; o >>= 1) mx = fmaxf(mx, __shfl_xor_sync(0xffffffffu, mx, o));
            v0 = expf(v0 - mx); v1 = expf(v1 - mx); v2 = expf(v2 - mx); v3 = expf(v3 - mx);
            float sum = v0 + v1 + v2 + v3;
            #pragma unroll
            for (int o = 16; o > 0; o >>= 1) sum += __shfl_xor_sync(0xffffffffu, sum, o);
            const float inv = 1.0f / sum;
            row[lane] = v0 * inv; row[lane + 32] = v1 * inv;
            row[lane + 64] = v2 * inv; row[lane + 96] = v3 * inv;
        }
    }
    __syncthreads();

    {
        const int tq2 = tid >> 4, tx2 = tid & 15;
        float acc[4][4];
        #pragma unroll
        for (int i = 0; i < 4; i++)
            #pragma unroll
            for (int t = 0; t < 4; t++) acc[i][t] = 0.f;
        #pragma unroll 4
        for (int j = 0; j < B_; j++) {
            const float4 rb = *(const float4*)(sV + j * DH_ + tx2 * 4);
            const float bb[4] = {rb.x, rb.y, rb.z, rb.w};
            float pa[4];
            #pragma unroll
            for (int i = 0; i < 4; i++) pa[i] = sS[(tq2 * 4 + i) * B_ + j];
            #pragma unroll
            for (int i = 0; i < 4; i++)
                #pragma unroll
                for (int t = 0; t < 4; t++) acc[i][t] += pa[i] * bb[t];
        }
        float* outbase = g_att + ((size_t)(s * N_ + n)) * Q_ * INNER_;
        #pragma unroll
        for (int i = 0; i < 4; i++) {
            float4 v = make_float4(acc[i][0], acc[i][1], acc[i][2], acc[i][3]);
            *(float4*)(outbase + (size_t)(tq2 * 4 + i) * INNER_ + h * DH_ + tx2 * 4) = v;
        }
    }
}

// ---------------- LayerNorm (fp32 y + half y) ----------------
__global__ __launch_bounds__(256) void ln_kernel(
    const float* __restrict__ gamma, const float* __restrict__ beta)
{
    const int r = blockIdx.x;
    const float* xr = g_att + (size_t)r * INNER_;
    float* yr = g_y + (size_t)r * INNER_;
    const int tid = threadIdx.x;
    const int warp = tid >> 5, lane = tid & 31;

    float v[4];
    float sum = 0.f;
    #pragma unroll
    for (int i = 0; i < 4; i++) { v[i] = xr[tid + i * 256]; sum += v[i]; }

    __shared__ float red[8];
    #pragma unroll
    for (int o = 16; o > 0; o >>= 1) sum += __shfl_xor_sync(0xffffffffu, sum, o);
    if (lane == 0) red[warp] = sum;
    __syncthreads();
    float tot = red[lane & 7];
    #pragma unroll
    for (int o = 4; o > 0; o >>= 1) tot += __shfl_xor_sync(0xffffffffu, tot, o);
    float mean = tot * (1.0f / 1024.0f);

    float sq = 0.f;
    #pragma unroll
    for (int i = 0; i < 4; i++) { float d = v[i] - mean; sq += d * d; }
    #pragma unroll
    for (int o = 16; o > 0; o >>= 1) sq += __shfl_xor_sync(0xffffffffu, sq, o);
    __syncthreads();
    if (lane == 0) red[warp] = sq;
    __syncthreads();
    float tot2 = red[lane & 7];
    #pragma unroll
    for (int o = 4; o > 0; o >>= 1) tot2 += __shfl_xor_sync(0xffffffffu, tot2, o);
    float var = tot2 * (1.0f / 1024.0f);
    float inv = rsqrtf(var + 1e-5f);

    #pragma unroll
    for (int i = 0; i < 4; i++) {
        int c = tid + i * 256;
        float yv = (v[i] - mean) * inv * gamma[c] + beta[c];
        yr[c] = yv;
        g_yh[(size_t)r * INNER_ + c] = __float2half(yv);
    }
}

// ---------------- launch ----------------
extern "C" void kernel_launch(void* const* d_in, const int* in_sizes, int n_in,
                              void* d_out, int out_size)
{
    const float* x    = (const float*)d_in[0];
    const int*   mask = (const int*)  d_in[1];
    const float* q    = (const float*)d_in[2];
    const float* W_kv = (const float*)d_in[3];
    const float* ln_g = (const float*)d_in[4];
    const float* ln_b = (const float*)d_in[5];
    const float* W1   = (const float*)d_in[6];
    const float* b1   = (const float*)d_in[7];
    const float* W2   = (const float*)d_in[8];
    const float* b2   = (const float*)d_in[9];
    float* out = (float*)d_out;
    (void)in_sizes; (void)n_in; (void)out_size;

    float *kv, *y;
    __half *xa, *wkt, *w1t, *w2t, *yh, *hh;
    cudaGetSymbolAddress((void**)&kv,  g_kv);
    cudaGetSymbolAddress((void**)&y,   g_y);
    cudaGetSymbolAddress((void**)&xa,  g_xa);
    cudaGetSymbolAddress((void**)&wkt, g_wkt);
    cudaGetSymbolAddress((void**)&w1t, g_w1t);
    cudaGetSymbolAddress((void**)&w2t, g_w2t);
    cudaGetSymbolAddress((void**)&yh,  g_yh);
    cudaGetSymbolAddress((void**)&hh,  g_hh);

    cudaFuncSetAttribute(attn_kernel,    cudaFuncAttributeMaxDynamicSharedMemorySize, ATTN_SMEM);
    cudaFuncSetAttribute(mma_gemm,       cudaFuncAttributeMaxDynamicSharedMemorySize, GEMM_SMEM);
    cudaFuncSetAttribute(mma_gemm_geglu, cudaFuncAttributeMaxDynamicSharedMemorySize, GEGLU_SMEM);

    // prep
    prep_x_kernel<<<(KVROWS_ * (size_t)D_) / 4 / 256, 256>>>(x);
    {
        dim3 b(32, 8);
        tsplit_kernel<<<dim3(KVW_ / 32, D_ / 32), b>>>(W_kv, wkt, D_, KVW_);
        tsplit_kernel<<<dim3(FF2_ / 32, INNER_ / 32), b>>>(W1, w1t, INNER_, FF2_);
        tsplit_kernel<<<dim3(INNER_ / 32, FFH_ / 32), b>>>(W2, w2t, FFH_, INNER_);
    }
    // 1) kv = x_t @ W_kv
    mma_gemm<<<(KVROWS_ / 128) * (KVW_ / 128), 256, GEMM_SMEM>>>(
        xa, wkt, kv, KVW_, D_, 0, nullptr, nullptr);
    // 2) attention -> g_att
    attn_kernel<<<S_ * N_ * HEADS_, 256, ATTN_SMEM>>>(q, mask);
    // 3) LayerNorm -> g_y (+ half)
    ln_kernel<<<ROWS_, 256>>>(ln_g, ln_b);
    // 4+5) u = y@W1 + b1; h = geglu(u)  (fused)
    mma_gemm_geglu<<<(ROWS_ / 128) * (FFH_ / 128), 256, GEGLU_SMEM>>>(yh, w1t, b1);
    // 6) out = h@W2 + b2 + y
    mma_gemm<<<(ROWS_ / 128) * (INNER_ / 128), 256, GEMM_SMEM>>>(
        hh, w2t, out, INNER_, FFH_, 2, b2, y);
}

// round 8
// speedup vs baseline: 3.0994x; 1.1776x over previous
#include <cuda_runtime.h>
#include <cuda_fp16.h>
#include <math.h>
#include <stdint.h>

// ---------------- problem constants ----------------
#define S_     8
#define B_     128
#define N_     32
#define D_     1024
#define HEADS_ 16
#define DH_    64
#define Q_     64
#define INNER_ 1024
#define KVW_   2048
#define FFH_   4096
#define FF2_   8192
#define ROWS_  (S_*N_*Q_)    // 16384
#define KVROWS_ (S_*N_*B_)   // 32768

// ---------------- scratch ----------------
__device__ float g_att[(size_t)ROWS_*INNER_];
__device__ float g_y  [(size_t)ROWS_*INNER_];

__device__ __half g_kvh[(size_t)KVROWS_*KVW_];   // kv in fp16
__device__ __half g_xa [(size_t)KVROWS_*D_];
__device__ __half g_wkt[(size_t)KVW_*D_];
__device__ __half g_w1t[(size_t)FF2_*INNER_];
__device__ __half g_w2t[(size_t)INNER_*FFH_];
__device__ __half g_yh [(size_t)ROWS_*INNER_];
__device__ __half g_hh [(size_t)ROWS_*FFH_];

// ---------------- helpers ----------------
__device__ __forceinline__ uint32_t smem_u32(const void* p) {
    uint32_t a;
    asm("{ .reg .u64 t; cvta.to.shared.u64 t, %1; cvt.u32.u64 %0, t; }" : "=r"(a) : "l"(p));
    return a;
}
__device__ __forceinline__ void ldsm_x4(uint32_t (&r)[4], uint32_t a) {
    asm volatile("ldmatrix.sync.aligned.m8n8.x4.shared.b16 {%0,%1,%2,%3}, [%4];"
        : "=r"(r[0]), "=r"(r[1]), "=r"(r[2]), "=r"(r[3]) : "r"(a));
}
__device__ __forceinline__ void mma16816(float (&c)[4], const uint32_t (&a)[4],
                                         uint32_t b0, uint32_t b1) {
    asm volatile("mma.sync.aligned.m16n8k16.row.col.f32.f16.f16.f32 "
        "{%0,%1,%2,%3}, {%4,%5,%6,%7}, {%8,%9}, {%0,%1,%2,%3};"
        : "+f"(c[0]), "+f"(c[1]), "+f"(c[2]), "+f"(c[3])
        : "r"(a[0]), "r"(a[1]), "r"(a[2]), "r"(a[3]), "r"(b0), "r"(b1));
}
// swizzled shared offset: row * pitch, 16B-chunk XOR by (row&7)
__device__ __forceinline__ uint32_t swz(uint32_t row, uint32_t cb, uint32_t pitch) {
    return row * pitch + (((cb) & ~15u) ^ ((row & 7u) * 16u)) + ((cb) & 15u);
}

// ---------------- common GEMM tile constants ----------------
#define BKC 64
#define TILE_B 16384                     // 128 rows x 128 bytes
#define STAGE2_B (2*TILE_B)
#define STAGE3_B (3*TILE_B)
#define GEMM_SMEM  (1024 + 3*STAGE2_B)   // ~97 KB
#define GEGLU_SMEM (1024 + 3*STAGE3_B)   // ~145 KB

// ---------------- fp16 GEMM: C = A@B^T ----------------
// mode 0: write __half to C; mode 2: fp32 +bias[n] +addmat[m][n]
__global__ __launch_bounds__(256) void mma_gemm(
    const __half* __restrict__ Ah, const __half* __restrict__ Bh,
    void* __restrict__ Cv, int Nn, int K, int mode,
    const float* __restrict__ bias, const float* __restrict__ addmat)
{
    extern __shared__ char smem[];
    const uint32_t tiles = (smem_u32(smem) + 1023u) & ~1023u;
    const int tid = threadIdx.x;
    const int wid = tid >> 5, lid = tid & 31;

    const int tiles_n = Nn >> 7;
    const int bid = blockIdx.x;
    const int group = bid / (16 * tiles_n);
    const int rem = bid - group * 16 * tiles_n;
    const int row0 = ((group << 4) + (rem & 15)) << 7;
    const int col0 = (rem >> 4) << 7;

    const int wm = wid & 1;
    const int wn = wid >> 1;

    const __half* a0 = Ah + (size_t)row0 * K;
    const __half* b0 = Bh + (size_t)col0 * K;
    const int nch = K / BKC;

    auto load_stage = [&](int st, int kc) {
        const uint32_t sb = tiles + st * STAGE2_B;
        const int kB = kc * BKC * 2;
        #pragma unroll
        for (int j = 0; j < 4; j++) {
            const int i = j * 256 + tid;
            const int r = i >> 3;
            const int c = i & 7;
            const uint32_t d = (uint32_t)(r * 128 + ((c * 16) ^ ((r & 7) * 16)));
            const size_t go = (size_t)r * K * 2 + kB + c * 16;
            asm volatile("cp.async.cg.shared.global [%0], [%1], 16;"
                :: "r"(sb + d), "l"((const char*)a0 + go));
            asm volatile("cp.async.cg.shared.global [%0], [%1], 16;"
                :: "r"(sb + TILE_B + d), "l"((const char*)b0 + go));
        }
        asm volatile("cp.async.commit_group;" ::: "memory");
    };

    float acc[4][4][4];
    #pragma unroll
    for (int i = 0; i < 4; i++)
        #pragma unroll
        for (int j = 0; j < 4; j++)
            #pragma unroll
            for (int t = 0; t < 4; t++) acc[i][j][t] = 0.f;

    const int lr = lid & 7;
    const int g  = lid >> 3;
    const uint32_t laneXor = (uint32_t)(lr * 16);

    load_stage(0, 0); load_stage(1, 1); load_stage(2, 2);

    for (int kc = 0; kc < nch; kc++) {
        const int st = kc % 3;
        asm volatile("cp.async.wait_group 2;" ::: "memory");
        __syncthreads();
        const uint32_t sb = tiles + st * STAGE2_B;
        #pragma unroll
        for (int kk = 0; kk < 4; kk++) {
            const uint32_t cx = (uint32_t)((kk * 32 + (g >> 1) * 16)) ^ laneXor;
            uint32_t a[4][4];
            #pragma unroll
            for (int i = 0; i < 4; i++) {
                const uint32_t row = (uint32_t)(wm * 64 + i * 16 + lr + (g & 1) * 8);
                ldsm_x4(a[i], sb + row * 128 + cx);
            }
            uint32_t b[2][4];
            #pragma unroll
            for (int jj = 0; jj < 2; jj++) {
                const uint32_t row = (uint32_t)(wn * 32 + jj * 16 + lr + (g & 1) * 8);
                ldsm_x4(b[jj], sb + TILE_B + row * 128 + cx);
            }
            #pragma unroll
            for (int i = 0; i < 4; i++)
                #pragma unroll
                for (int jj = 0; jj < 2; jj++) {
                    mma16816(acc[i][2*jj],   a[i], b[jj][0], b[jj][2]);
                    mma16816(acc[i][2*jj+1], a[i], b[jj][1], b[jj][3]);
                }
        }
        __syncthreads();
        if (kc + 3 < nch) load_stage(st, kc + 3);
    }

    const int lr4 = lid >> 2, lc2 = (lid & 3) * 2;
    #pragma unroll
    for (int i = 0; i < 4; i++) {
        #pragma unroll
        for (int j = 0; j < 4; j++) {
            const int mr = row0 + wm * 64 + i * 16 + lr4;
            const int cc = col0 + wn * 32 + j * 8 + lc2;
            float2 v0 = make_float2(acc[i][j][0], acc[i][j][1]);
            float2 v1 = make_float2(acc[i][j][2], acc[i][j][3]);
            if (mode == 0) {
                __half* Ch = (__half*)Cv;
                *(__half2*)(Ch + (size_t)mr * Nn + cc) =
                    __halves2half2(__float2half(v0.x), __float2half(v0.y));
                *(__half2*)(Ch + (size_t)(mr + 8) * Nn + cc) =
                    __halves2half2(__float2half(v1.x), __float2half(v1.y));
            } else {
                float* C = (float*)Cv;
                const float2 bb = *(const float2*)(bias + cc);
                const float2 am0 = *(const float2*)(addmat + (size_t)mr * Nn + cc);
                const float2 am1 = *(const float2*)(addmat + (size_t)(mr + 8) * Nn + cc);
                v0.x += bb.x + am0.x; v0.y += bb.y + am0.y;
                v1.x += bb.x + am1.x; v1.y += bb.y + am1.y;
                *(float2*)(C + (size_t)mr * Nn + cc) = v0;
                *(float2*)(C + (size_t)(mr + 8) * Nn + cc) = v1;
            }
        }
    }
}

// ---------------- fused W1-GEMM + GEGLU ----------------
__global__ __launch_bounds__(256) void mma_gemm_geglu(
    const __half* __restrict__ Ah,
    const __half* __restrict__ Bt,
    const float* __restrict__ bias)
{
    extern __shared__ char smem[];
    const uint32_t tiles = (smem_u32(smem) + 1023u) & ~1023u;
    const int tid = threadIdx.x;
    const int wid = tid >> 5, lid = tid & 31;

    const int tiles_n = FFH_ >> 7;
    const int bid = blockIdx.x;
    const int group = bid / (16 * tiles_n);
    const int rem = bid - group * 16 * tiles_n;
    const int row0 = ((group << 4) + (rem & 15)) << 7;
    const int col0 = (rem >> 4) << 7;

    const int wm = wid & 1;
    const int wn = wid >> 1;
    const int K = INNER_;

    const __half* a0 = Ah + (size_t)row0 * K;
    const __half* ba = Bt + (size_t)col0 * K;
    const __half* bg = Bt + (size_t)(FFH_ + col0) * K;
    const int nch = K / BKC;

    auto load_stage = [&](int st, int kc) {
        const uint32_t sb = tiles + st * STAGE3_B;
        const int kB = kc * BKC * 2;
        #pragma unroll
        for (int j = 0; j < 4; j++) {
            const int i = j * 256 + tid;
            const int r = i >> 3;
            const int c = i & 7;
            const uint32_t d = (uint32_t)(r * 128 + ((c * 16) ^ ((r & 7) * 16)));
            const size_t go = (size_t)r * K * 2 + kB + c * 16;
            asm volatile("cp.async.cg.shared.global [%0], [%1], 16;"
                :: "r"(sb + d), "l"((const char*)a0 + go));
            asm volatile("cp.async.cg.shared.global [%0], [%1], 16;"
                :: "r"(sb + TILE_B + d), "l"((const char*)ba + go));
            asm volatile("cp.async.cg.shared.global [%0], [%1], 16;"
                :: "r"(sb + 2*TILE_B + d), "l"((const char*)bg + go));
        }
        asm volatile("cp.async.commit_group;" ::: "memory");
    };

    float acca[4][4][4], accg[4][4][4];
    #pragma unroll
    for (int i = 0; i < 4; i++)
        #pragma unroll
        for (int j = 0; j < 4; j++)
            #pragma unroll
            for (int t = 0; t < 4; t++) { acca[i][j][t] = 0.f; accg[i][j][t] = 0.f; }

    const int lr = lid & 7;
    const int g  = lid >> 3;
    const uint32_t laneXor = (uint32_t)(lr * 16);

    load_stage(0, 0); load_stage(1, 1); load_stage(2, 2);

    for (int kc = 0; kc < nch; kc++) {
        const int st = kc % 3;
        asm volatile("cp.async.wait_group 2;" ::: "memory");
        __syncthreads();
        const uint32_t sb = tiles + st * STAGE3_B;
        #pragma unroll
        for (int kk = 0; kk < 4; kk++) {
            const uint32_t cx = (uint32_t)((kk * 32 + (g >> 1) * 16)) ^ laneXor;
            uint32_t a[4][4];
            #pragma unroll
            for (int i = 0; i < 4; i++) {
                const uint32_t row = (uint32_t)(wm * 64 + i * 16 + lr + (g & 1) * 8);
                ldsm_x4(a[i], sb + row * 128 + cx);
            }
            uint32_t bA[2][4], bG[2][4];
            #pragma unroll
            for (int jj = 0; jj < 2; jj++) {
                const uint32_t row = (uint32_t)(wn * 32 + jj * 16 + lr + (g & 1) * 8);
                ldsm_x4(bA[jj], sb + TILE_B + row * 128 + cx);
                ldsm_x4(bG[jj], sb + 2*TILE_B + row * 128 + cx);
            }
            #pragma unroll
            for (int i = 0; i < 4; i++)
                #pragma unroll
                for (int jj = 0; jj < 2; jj++) {
                    mma16816(acca[i][2*jj],   a[i], bA[jj][0], bA[jj][2]);
                    mma16816(acca[i][2*jj+1], a[i], bA[jj][1], bA[jj][3]);
                    mma16816(accg[i][2*jj],   a[i], bG[jj][0], bG[jj][2]);
                    mma16816(accg[i][2*jj+1], a[i], bG[jj][1], bG[jj][3]);
                }
        }
        __syncthreads();
        if (kc + 3 < nch) load_stage(st, kc + 3);
    }

    const int lr4 = lid >> 2, lc2 = (lid & 3) * 2;
    #pragma unroll
    for (int i = 0; i < 4; i++) {
        #pragma unroll
        for (int j = 0; j < 4; j++) {
            const int mr = row0 + wm * 64 + i * 16 + lr4;
            const int cc = col0 + wn * 32 + j * 8 + lc2;
            const float2 bba = *(const float2*)(bias + cc);
            const float2 bbg = *(const float2*)(bias + FFH_ + cc);
            #pragma unroll
            for (int half_i = 0; half_i < 2; half_i++) {
                const int m = mr + half_i * 8;
                float av0 = acca[i][j][2*half_i]   + bba.x;
                float av1 = acca[i][j][2*half_i+1] + bba.y;
                float gv0 = accg[i][j][2*half_i]   + bbg.x;
                float gv1 = accg[i][j][2*half_i+1] + bbg.y;
                float h0 = av0 * (0.5f * gv0 * (1.0f + erff(gv0 * 0.70710678118654752f)));
                float h1 = av1 * (0.5f * gv1 * (1.0f + erff(gv1 * 0.70710678118654752f)));
                *(__half2*)(g_hh + (size_t)m * FFH_ + cc) =
                    __halves2half2(__float2half(h0), __float2half(h1));
            }
        }
    }
}

// ---------------- prep: x remap -> half ----------------
__global__ __launch_bounds__(256) void prep_x_kernel(const float* __restrict__ x)
{
    const size_t i = (size_t)blockIdx.x * 256 + threadIdx.x;
    const size_t e = i << 2;
    const int m = (int)(e >> 10);
    const int col = (int)(e & 1023);
    const int s = m >> 12, rm = m & 4095, n = rm >> 7, b = rm & 127;
    const float4 v = *(const float4*)(x + (((size_t)((s * 128 + b) * 32 + n)) << 10) + col);
    *(__half2*)(g_xa + e)     = __halves2half2(__float2half(v.x), __float2half(v.y));
    *(__half2*)(g_xa + e + 2) = __halves2half2(__float2half(v.z), __float2half(v.w));
}

// ---------------- prep: transpose W -> half ----------------
__global__ __launch_bounds__(256) void tsplit_kernel(
    const float* __restrict__ in, __half* __restrict__ oh, int R, int C)
{
    __shared__ float tile[32][33];
    const int r0 = blockIdx.y * 32, c0 = blockIdx.x * 32;
    const int tx = threadIdx.x, ty = threadIdx.y;
    #pragma unroll
    for (int j = ty; j < 32; j += 8)
        tile[j][tx] = in[(size_t)(r0 + j) * C + c0 + tx];
    __syncthreads();
    #pragma unroll
    for (int j = ty; j < 32; j += 8)
        oh[(size_t)(c0 + j) * R + r0 + tx] = __float2half(tile[tx][j]);
}

// ---------------- tensor-core attention ----------------
// smem bytes: [0,8K) Qh | [8K,16K) Ql | [16K,32K) K | [32K,64K) S(fp32) | [64K,+512) mask
// after phase 1: [0,16K) -> P (half, pitch 256), [16K,32K) -> Vt (half, pitch 256)
#define OQH 0
#define OQL 8192
#define OKT 16384
#define OS  32768
#define OMK 65536
#define OP  0
#define OVT 16384
#define ATTN_SMEM (65536 + 512)

__global__ __launch_bounds__(256) void attn_kernel(
    const float* __restrict__ q, const int* __restrict__ mask)
{
    extern __shared__ char smem[];
    const uint32_t sbase = smem_u32(smem);
    float* sS = (float*)(smem + OS);
    int* sMask = (int*)(smem + OMK);

    const int blk = blockIdx.x;
    const int s = blk / (N_ * HEADS_);
    const int n = (blk / HEADS_) % N_;
    const int h = blk % HEADS_;
    const int tid = threadIdx.x;
    const int wid = tid >> 5, lid = tid & 31;
    const int lr = lid & 7, g = lid >> 3;
    const int lr4 = lid >> 2, lc2 = (lid & 3) * 2;

    const __half* kvbase = g_kvh + ((size_t)(s * N_ + n)) * B_ * KVW_;

    // --- phase 0: load Q (split hi/lo), K, mask ---
    #pragma unroll
    for (int j = 0; j < 4; j++) {
        const int i = j * 256 + tid;          // 1024 float4s
        const int qi = i >> 4, c4 = i & 15;
        const float4 v = *(const float4*)(q + qi * INNER_ + h * DH_ + c4 * 4);
        __half h0 = __float2half(v.x), h1 = __float2half(v.y);
        __half h2 = __float2half(v.z), h3 = __float2half(v.w);
        __half l0 = __float2half(v.x - __half2float(h0));
        __half l1 = __float2half(v.y - __half2float(h1));
        __half l2 = __float2half(v.z - __half2float(h2));
        __half l3 = __float2half(v.w - __half2float(h3));
        const uint32_t off = swz((uint32_t)qi, (uint32_t)(c4 * 8), 128);
        *(__half2*)(smem + OQH + off)     = __halves2half2(h0, h1);
        *(__half2*)(smem + OQH + off + 4) = __halves2half2(h2, h3);
        *(__half2*)(smem + OQL + off)     = __halves2half2(l0, l1);
        *(__half2*)(smem + OQL + off + 4) = __halves2half2(l2, l3);
    }
    #pragma unroll
    for (int j = 0; j < 4; j++) {
        const int i = j * 256 + tid;          // 1024 16B chunks
        const int jr = i >> 3, c = i & 7;
        const uint4 v = *(const uint4*)(kvbase + (size_t)jr * KVW_ + h * DH_ + c * 8);
        *(uint4*)(smem + OKT + swz((uint32_t)jr, (uint32_t)(c * 16), 128)) = v;
    }
    if (tid < 128) sMask[tid] = mask[s * B_ + tid];
    __syncthreads();

    // --- phase 1: sim = Q@K^T (Q hi/lo split) ---
    {
        const int mrow0 = (wid & 3) * 16;
        const int nbase = (wid >> 2) * 64;
        float acc[8][4];
        #pragma unroll
        for (int f = 0; f < 8; f++)
            #pragma unroll
            for (int t = 0; t < 4; t++) acc[f][t] = 0.f;
        const uint32_t laneXor = (uint32_t)(lr * 16);
        #pragma unroll
        for (int kk = 0; kk < 4; kk++) {
            const uint32_t cx = (uint32_t)((kk * 32 + (g >> 1) * 16)) ^ laneXor;
            const uint32_t arow = (uint32_t)(mrow0 + lr + (g & 1) * 8);
            uint32_t aH[4], aL[4];
            ldsm_x4(aH, sbase + OQH + arow * 128 + cx);
            ldsm_x4(aL, sbase + OQL + arow * 128 + cx);
            uint32_t b[4][4];
            #pragma unroll
            for (int nn = 0; nn < 4; nn++) {
                const uint32_t brow = (uint32_t)(nbase + nn * 16 + lr + (g & 1) * 8);
                ldsm_x4(b[nn], sbase + OKT + brow * 128 + cx);
            }
            #pragma unroll
            for (int nn = 0; nn < 4; nn++) {
                mma16816(acc[2*nn],   aH, b[nn][0], b[nn][2]);
                mma16816(acc[2*nn+1], aH, b[nn][1], b[nn][3]);
            }
            #pragma unroll
            for (int nn = 0; nn < 4; nn++) {
                mma16816(acc[2*nn],   aL, b[nn][0], b[nn][2]);
                mma16816(acc[2*nn+1], aL, b[nn][1], b[nn][3]);
            }
        }
        #pragma unroll
        for (int f = 0; f < 8; f++) {
            const int c0 = nbase + f * 8 + lc2;
            const int r0 = mrow0 + lr4;
            const bool m0 = (sMask[c0] == 0), m1 = (sMask[c0 + 1] == 0);
            sS[r0 * B_ + c0]           = m0 ? -1e10f : acc[f][0] * 0.125f;
            sS[r0 * B_ + c0 + 1]       = m1 ? -1e10f : acc[f][1] * 0.125f;
            sS[(r0 + 8) * B_ + c0]     = m0 ? -1e10f : acc[f][2] * 0.125f;
            sS[(r0 + 8) * B_ + c0 + 1] = m1 ? -1e10f : acc[f][3] * 0.125f;
        }
    }
    __syncthreads();

    // --- load V transposed into OVT (overwrites K region) ---
    {
        const int j = tid & 127, dvb = (tid >> 7) * 32;
        const __half* src = kvbase + (size_t)j * KVW_ + INNER_ + h * DH_ + dvb;
        #pragma unroll
        for (int c = 0; c < 4; c++) {
            union { uint4 u; __half hv[8]; } vv;
            vv.u = *(const uint4*)(src + c * 8);
            #pragma unroll
            for (int e = 0; e < 8; e++) {
                const int dv = dvb + c * 8 + e;
                *(__half*)(smem + OVT + swz((uint32_t)dv, (uint32_t)(j * 2), 256)) = vv.hv[e];
            }
        }
    }

    // --- softmax (each warp owns 8 rows) ---
    {
        for (int r = wid * 8; r < wid * 8 + 8; r++) {
            float* row = sS + r * B_;
            float v0 = row[lid], v1 = row[lid + 32], v2 = row[lid + 64], v3 = row[lid + 96];
            float mx = fmaxf(fmaxf(v0, v1), fmaxf(v2, v3));
            #pragma unroll
            for (int o = 16; o > 0; o >>= 1) mx = fmaxf(mx, __shfl_xor_sync(0xffffffffu, mx, o));
            v0 = expf(v0 - mx); v1 = expf(v1 - mx); v2 = expf(v2 - mx); v3 = expf(v3 - mx);
            float sum = v0 + v1 + v2 + v3;
            #pragma unroll
            for (int o = 16; o > 0; o >>= 1) sum += __shfl_xor_sync(0xffffffffu, sum, o);
            const float inv = 1.0f / sum;
            row[lid] = v0 * inv; row[lid + 32] = v1 * inv;
            row[lid + 64] = v2 * inv; row[lid + 96] = v3 * inv;
        }
    }
    __syncthreads();

    // --- convert P -> half into OP (overwrites Q region) ---
    #pragma unroll
    for (int j = 0; j < 16; j++) {
        const int i = j * 256 + tid;          // 4096 half2
        const int r = i >> 6, cp = i & 63;
        const float2 v = *(const float2*)(sS + r * B_ + cp * 2);
        *(__half2*)(smem + OP + swz((uint32_t)r, (uint32_t)(cp * 4), 256)) =
            __halves2half2(__float2half(v.x), __float2half(v.y));
    }
    __syncthreads();

    // --- phase 3: out = P@V ---
    {
        const int mrow0 = (wid & 3) * 16;
        const int nb = (wid >> 2) * 32;
        float acc[4][4];
        #pragma unroll
        for (int f = 0; f < 4; f++)
            #pragma unroll
            for (int t = 0; t < 4; t++) acc[f][t] = 0.f;
        const uint32_t laneXor = (uint32_t)(lr * 16);
        #pragma unroll
        for (int kk = 0; kk < 8; kk++) {
            const uint32_t cx = (uint32_t)((kk * 32 + (g >> 1) * 16)) ^ laneXor;
            const uint32_t arow = (uint32_t)(mrow0 + lr + (g & 1) * 8);
            uint32_t a[4];
            ldsm_x4(a, sbase + OP + arow * 256 + cx);
            uint32_t b[2][4];
            #pragma unroll
            for (int nn = 0; nn < 2; nn++) {
                const uint32_t brow = (uint32_t)(nb + nn * 16 + lr + (g & 1) * 8);
                ldsm_x4(b[nn], sbase + OVT + brow * 256 + cx);
            }
            #pragma unroll
            for (int nn = 0; nn < 2; nn++) {
                mma16816(acc[2*nn],   a, b[nn][0], b[nn][2]);
                mma16816(acc[2*nn+1], a, b[nn][1], b[nn][3]);
            }
        }
        float* outbase = g_att + ((size_t)(s * N_ + n)) * Q_ * INNER_ + h * DH_;
        #pragma unroll
        for (int f = 0; f < 4; f++) {
            const int dv = nb + f * 8 + lc2;
            const int r0 = mrow0 + lr4;
            *(float2*)(outbase + (size_t)r0 * INNER_ + dv) =
                make_float2(acc[f][0], acc[f][1]);
            *(float2*)(outbase + (size_t)(r0 + 8) * INNER_ + dv) =
                make_float2(acc[f][2], acc[f][3]);
        }
    }
}

// ---------------- LayerNorm (fp32 y + half y) ----------------
__global__ __launch_bounds__(256) void ln_kernel(
    const float* __restrict__ gamma, const float* __restrict__ beta)
{
    const int r = blockIdx.x;
    const float* xr = g_att + (size_t)r * INNER_;
    float* yr = g_y + (size_t)r * INNER_;
    const int tid = threadIdx.x;
    const int warp = tid >> 5, lane = tid & 31;

    float v[4];
    float sum = 0.f;
    #pragma unroll
    for (int i = 0; i < 4; i++) { v[i] = xr[tid + i * 256]; sum += v[i]; }

    __shared__ float red[8];
    #pragma unroll
    for (int o = 16; o > 0; o >>= 1) sum += __shfl_xor_sync(0xffffffffu, sum, o);
    if (lane == 0) red[warp] = sum;
    __syncthreads();
    float tot = red[lane & 7];
    #pragma unroll
    for (int o = 4; o > 0; o >>= 1) tot += __shfl_xor_sync(0xffffffffu, tot, o);
    float mean = tot * (1.0f / 1024.0f);

    float sq = 0.f;
    #pragma unroll
    for (int i = 0; i < 4; i++) { float d = v[i] - mean; sq += d * d; }
    #pragma unroll
    for (int o = 16; o > 0; o >>= 1) sq += __shfl_xor_sync(0xffffffffu, sq, o);
    __syncthreads();
    if (lane == 0) red[warp] = sq;
    __syncthreads();
    float tot2 = red[lane & 7];
    #pragma unroll
    for (int o = 4; o > 0; o >>= 1) tot2 += __shfl_xor_sync(0xffffffffu, tot2, o);
    float var = tot2 * (1.0f / 1024.0f);
    float inv = rsqrtf(var + 1e-5f);

    #pragma unroll
    for (int i = 0; i < 4; i++) {
        int c = tid + i * 256;
        float yv = (v[i] - mean) * inv * gamma[c] + beta[c];
        yr[c] = yv;
        g_yh[(size_t)r * INNER_ + c] = __float2half(yv);
    }
}

// ---------------- launch ----------------
extern "C" void kernel_launch(void* const* d_in, const int* in_sizes, int n_in,
                              void* d_out, int out_size)
{
    const float* x    = (const float*)d_in[0];
    const int*   mask = (const int*)  d_in[1];
    const float* q    = (const float*)d_in[2];
    const float* W_kv = (const float*)d_in[3];
    const float* ln_g = (const float*)d_in[4];
    const float* ln_b = (const float*)d_in[5];
    const float* W1   = (const float*)d_in[6];
    const float* b1   = (const float*)d_in[7];
    const float* W2   = (const float*)d_in[8];
    const float* b2   = (const float*)d_in[9];
    float* out = (float*)d_out;
    (void)in_sizes; (void)n_in; (void)out_size;

    float *y;
    __half *kvh, *xa, *wkt, *w1t, *w2t, *yh, *hh;
    cudaGetSymbolAddress((void**)&y,   g_y);
    cudaGetSymbolAddress((void**)&kvh, g_kvh);
    cudaGetSymbolAddress((void**)&xa,  g_xa);
    cudaGetSymbolAddress((void**)&wkt, g_wkt);
    cudaGetSymbolAddress((void**)&w1t, g_w1t);
    cudaGetSymbolAddress((void**)&w2t, g_w2t);
    cudaGetSymbolAddress((void**)&yh,  g_yh);
    cudaGetSymbolAddress((void**)&hh,  g_hh);

    cudaFuncSetAttribute(attn_kernel,    cudaFuncAttributeMaxDynamicSharedMemorySize, ATTN_SMEM);
    cudaFuncSetAttribute(mma_gemm,       cudaFuncAttributeMaxDynamicSharedMemorySize, GEMM_SMEM);
    cudaFuncSetAttribute(mma_gemm_geglu, cudaFuncAttributeMaxDynamicSharedMemorySize, GEGLU_SMEM);

    // prep
    prep_x_kernel<<<(KVROWS_ * (size_t)D_) / 4 / 256, 256>>>(x);
    {
        dim3 b(32, 8);
        tsplit_kernel<<<dim3(KVW_ / 32, D_ / 32), b>>>(W_kv, wkt, D_, KVW_);
        tsplit_kernel<<<dim3(FF2_ / 32, INNER_ / 32), b>>>(W1, w1t, INNER_, FF2_);
        tsplit_kernel<<<dim3(INNER_ / 32, FFH_ / 32), b>>>(W2, w2t, FFH_, INNER_);
    }
    // 1) kv = x_t @ W_kv -> half
    mma_gemm<<<(KVROWS_ / 128) * (KVW_ / 128), 256, GEMM_SMEM>>>(
        xa, wkt, kvh, KVW_, D_, 0, nullptr, nullptr);
    // 2) attention (tensor cores) -> g_att
    attn_kernel<<<S_ * N_ * HEADS_, 256, ATTN_SMEM>>>(q, mask);
    // 3) LayerNorm -> g_y (+ half)
    ln_kernel<<<ROWS_, 256>>>(ln_g, ln_b);
    // 4+5) fused W1 GEMM + GEGLU -> g_hh
    mma_gemm_geglu<<<(ROWS_ / 128) * (FFH_ / 128), 256, GEGLU_SMEM>>>(yh, w1t, b1);
    // 6) out = h@W2 + b2 + y
    mma_gemm<<<(ROWS_ / 128) * (INNER_ / 128), 256, GEMM_SMEM>>>(
        hh, w2t, out, INNER_, FFH_, 2, b2, y);
}